// round 13
// baseline (speedup 1.0000x reference)
#include <cuda_runtime.h>
#include <math.h>

#define NB 2
#define LL 9216
#define NHH 4
#define CHK 144
#define NCHK 64
#define TOKS (NB*LL)

// ---------------- static scratch ----------------
__device__ float g_xe[TOKS*16];
__device__ float g_xm[TOKS*16];
__device__ float g_ye[(size_t)TOKS*64];
__device__ float g_fe[(size_t)TOKS*64];
__device__ float g_H [(size_t)TOKS*144];
__device__ float g_F [(size_t)TOKS*144];
__device__ unsigned char g_code[NB*NHH*LL];
__device__ int   g_perm[NB*NHH*LL];
__device__ float g_bsc[NB*NHH*LL];
__device__ float g_ret[(size_t)NB*NHH*LL*64];
// pre-gathered per-(seg,chunk) K rows ([xm*L2E (16) | F (144)]) and Y rows
__device__ float g_K[(size_t)8*64*144*160];
__device__ float g_Y[(size_t)8*64*144*64];

// ---------------- packed f32x2 helpers ----------------
typedef unsigned long long ull;
__device__ __forceinline__ ull pk2(float a, float b) {
    ull r; asm("mov.b64 %0,{%1,%2};" : "=l"(r) : "f"(a), "f"(b)); return r;
}
__device__ __forceinline__ void upk2(ull v, float& a, float& b) {
    asm("mov.b64 {%0,%1},%2;" : "=f"(a), "=f"(b) : "l"(v));
}
__device__ __forceinline__ ull fma2(ull a, ull b, ull c) {
    ull d; asm("fma.rn.f32x2 %0,%1,%2,%3;" : "=l"(d) : "l"(a), "l"(b), "l"(c)); return d;
}
__device__ __forceinline__ ull mul2_(ull a, ull b) {
    ull d; asm("mul.rn.f32x2 %0,%1,%2;" : "=l"(d) : "l"(a), "l"(b)); return d;
}
__device__ __forceinline__ float ex2f(float x) {
    float y; asm("ex2.approx.ftz.f32 %0,%1;" : "=f"(y) : "f"(x)); return y;
}
__device__ __forceinline__ float lg2f(float x) {
    float y; asm("lg2.approx.ftz.f32 %0,%1;" : "=f"(y) : "f"(x)); return y;
}
#define LOG2E 1.4426950408889634f
#define LN2   0.6931471805599453f

// =======================================================================
// K1: fused 3x3 SAME conv (144 out ch) + ReLU -> xe(16), ye(64), fe(64)
// =======================================================================
__global__ __launch_bounds__(288) void conv_kernel(
    const float* __restrict__ x,
    const float* __restrict__ wm, const float* __restrict__ bm,
    const float* __restrict__ wa, const float* __restrict__ ba,
    const float* __restrict__ wf, const float* __restrict__ bf)
{
    __shared__ float in_sh[8][3][100];
    __shared__ __align__(16) float w_sh[8][9][72];

    const int y    = blockIdx.x;
    const int n    = blockIdx.y;
    const int half = blockIdx.z;
    const int xcol = threadIdx.x;
    const int lane = threadIdx.y;
    const int tid  = xcol + 96*lane;
    const int coBase = half*72;

    ull acc2[12];
#pragma unroll
    for (int m = 0; m < 12; ++m) acc2[m] = 0ull;

    for (int cb = 0; cb < 8; ++cb) {
        __syncthreads();
        for (int idx = tid; idx < 8*3*98; idx += 288) {
            int c = idx / 294, rem = idx % 294, r = rem / 98, xx = rem % 98;
            int gy = y - 1 + r, gx = xx - 1, ci = cb*8 + c;
            float v = 0.f;
            if (gy >= 0 && gy < 96 && gx >= 0 && gx < 96)
                v = x[((n*64 + ci)*96 + gy)*96 + gx];
            in_sh[c][r][xx] = v;
        }
        for (int idx = tid; idx < 8*72*9; idx += 288) {
            int c = idx / 648, rem = idx % 648, tap = rem / 72, co_l = rem % 72;
            int co = coBase + co_l, ci = cb*8 + c;
            float w;
            if (co < 16)      w = wm[( co      *64 + ci)*9 + tap];
            else if (co < 80) w = wa[((co-16)*64 + ci)*9 + tap];
            else              w = wf[((co-80)*64 + ci)*9 + tap];
            w_sh[c][tap][co_l] = w;
        }
        __syncthreads();
#pragma unroll
        for (int c = 0; c < 8; ++c) {
            ull d[9];
            d[0] = pk2(in_sh[c][0][xcol],   in_sh[c][0][xcol]);
            d[1] = pk2(in_sh[c][0][xcol+1], in_sh[c][0][xcol+1]);
            d[2] = pk2(in_sh[c][0][xcol+2], in_sh[c][0][xcol+2]);
            d[3] = pk2(in_sh[c][1][xcol],   in_sh[c][1][xcol]);
            d[4] = pk2(in_sh[c][1][xcol+1], in_sh[c][1][xcol+1]);
            d[5] = pk2(in_sh[c][1][xcol+2], in_sh[c][1][xcol+2]);
            d[6] = pk2(in_sh[c][2][xcol],   in_sh[c][2][xcol]);
            d[7] = pk2(in_sh[c][2][xcol+1], in_sh[c][2][xcol+1]);
            d[8] = pk2(in_sh[c][2][xcol+2], in_sh[c][2][xcol+2]);
#pragma unroll
            for (int tap = 0; tap < 9; ++tap) {
                const ulonglong2* wp = (const ulonglong2*)&w_sh[c][tap][lane*24];
#pragma unroll
                for (int v = 0; v < 6; ++v) {
                    ulonglong2 w4 = wp[v];
                    acc2[2*v]   = fma2(d[tap], w4.x, acc2[2*v]);
                    acc2[2*v+1] = fma2(d[tap], w4.y, acc2[2*v+1]);
                }
            }
        }
    }

    const int tok = n*LL + y*96 + xcol;
    float acc[24];
#pragma unroll
    for (int m = 0; m < 12; ++m) upk2(acc2[m], acc[2*m], acc[2*m+1]);
#pragma unroll
    for (int m = 0; m < 24; ++m) {
        int co = coBase + lane*24 + m;
        if (co < 16) {
            g_xe[tok*16 + co] = fmaxf(acc[m] + bm[co], 0.f);
        } else if (co < 80) {
            g_ye[(size_t)tok*64 + (co-16)] = fmaxf(acc[m] + ba[co-16], 0.f);
        } else {
            g_fe[(size_t)tok*64 + (co-80)] = fmaxf(acc[m] + bf[co-80], 0.f);
        }
    }
}

// =======================================================================
// K2: LSH codes + normalized xm
// =======================================================================
__global__ __launch_bounds__(256) void code_kernel(const float* __restrict__ rot)
{
    __shared__ __align__(16) float rotT[4096];
    const int tid = threadIdx.x;
    for (int idx = tid; idx < 4096; idx += 256) {
        int hi = idx >> 4, f = idx & 15;
        rotT[idx] = rot[f*256 + hi];
    }
    __syncthreads();

    const int tg = blockIdx.x*256 + tid;
    const int n = tg / LL, t = tg % LL;

    const ulonglong2* ep = (const ulonglong2*)&g_xe[tg*16];
    ull ev[8];
#pragma unroll
    for (int i = 0; i < 4; ++i) { ulonglong2 v = ep[i]; ev[2*i] = v.x; ev[2*i+1] = v.y; }

    ull ssp = 0ull;
#pragma unroll
    for (int i = 0; i < 8; ++i) ssp = fma2(ev[i], ev[i], ssp);
    float slo, shi; upk2(ssp, slo, shi);
    float inv = 1.f / fmaxf(sqrtf(slo + shi), 5e-5f);
    ull invd = pk2(inv, inv);
    ulonglong2* xmp = (ulonglong2*)&g_xm[tg*16];
#pragma unroll
    for (int i = 0; i < 4; ++i) {
        ulonglong2 o;
        o.x = mul2_(ev[2*i], invd); o.y = mul2_(ev[2*i+1], invd);
        xmp[i] = o;
    }

#pragma unroll
    for (int h = 0; h < 4; ++h) {
        float best = -1e30f; int bi = 0;
        for (int i = 0; i < 64; ++i) {
            const ull* rr = (const ull*)&rotT[(h*64+i)*16];
            ull sp = 0ull;
#pragma unroll
            for (int j = 0; j < 8; ++j) sp = fma2(ev[j], rr[j], sp);
            float a, b; upk2(sp, a, b);
            float dd = a + b;
            if (dd > best) { best = dd; bi = i; }
        }
        g_code[(n*4+h)*LL + t] = (unsigned char)bi;
    }
}

// =======================================================================
// K3: per-(n,h) stable counting sort over 64 buckets -> g_perm
// =======================================================================
__global__ __launch_bounds__(256) void sort_kernel()
{
    const int seg = blockIdx.x;
    __shared__ int hist[64];
    __shared__ int running[64];
    __shared__ int wh[8][64];
    const int tid = threadIdx.x;
    const int w = tid >> 5, ln = tid & 31;

    if (tid < 64) hist[tid] = 0;
    __syncthreads();
    const unsigned char* code = &g_code[seg*LL];
    for (int t = tid; t < LL; t += 256) atomicAdd(&hist[code[t]], 1);
    __syncthreads();
    if (tid == 0) {
        int acc = 0;
        for (int b = 0; b < 64; ++b) { running[b] = acc; acc += hist[b]; }
    }
    __syncthreads();

    for (int tile = 0; tile < 36; ++tile) {
        int t = tile*256 + tid;
        int c = code[t];
        unsigned mask = __match_any_sync(0xffffffffu, c);
        int lanerank = __popc(mask & ((1u << ln) - 1u));
        ((int*)wh)[tid] = 0; ((int*)wh)[tid + 256] = 0;
        __syncthreads();
        if (lanerank == 0) wh[w][c] = __popc(mask);
        __syncthreads();
        int r = lanerank;
        for (int w2 = 0; w2 < w; ++w2) r += wh[w2][c];
        int pos = running[c] + r;
        __syncthreads();
        if (tid < 64) {
            int s = 0;
            for (int w2 = 0; w2 < 8; ++w2) s += wh[w2][tid];
            running[tid] += s;
        }
        __syncthreads();
        g_perm[seg*LL + pos] = t;
    }
}

// =======================================================================
// K4: H = relu(fe @ fc1_w^T + fc1_b)
// =======================================================================
__global__ __launch_bounds__(256) void hid_kernel(
    const float* __restrict__ fc1_w, const float* __restrict__ fc1_b)
{
    __shared__ __align__(16) float w_sh[144][68];
    __shared__ __align__(16) float fe_sh[32][68];
    __shared__ float b_sh[144];

    const int tid = threadIdx.x;
    for (int idx = tid; idx < 144*16; idx += 256) {
        int col = idx >> 4, kq = idx & 15;
        *(float4*)&w_sh[col][kq*4] = *(const float4*)&fc1_w[col*64 + kq*4];
    }
    if (tid < 144) b_sh[tid] = fc1_b[tid];
    const int tok0 = blockIdx.x * 32;
    for (int idx = tid; idx < 32*16; idx += 256) {
        int t = idx >> 4, kq = idx & 15;
        *(float4*)&fe_sh[t][kq*4] = *(const float4*)&g_fe[(size_t)(tok0+t)*64 + kq*4];
    }
    __syncthreads();

    const int cg = tid & 15;
    const int tg = tid >> 4;
    const int c0 = cg * 9;
    const int t0 = tg * 2;

    ull acc[18];
#pragma unroll
    for (int j = 0; j < 18; ++j) acc[j] = 0ull;

#pragma unroll
    for (int kk = 0; kk < 16; ++kk) {
        ulonglong2 f0 = *(const ulonglong2*)&fe_sh[t0][kk*4];
        ulonglong2 f1 = *(const ulonglong2*)&fe_sh[t0+1][kk*4];
#pragma unroll
        for (int j = 0; j < 9; ++j) {
            ulonglong2 w4 = *(const ulonglong2*)&w_sh[c0+j][kk*4];
            acc[j]   = fma2(f0.x, w4.x, acc[j]);
            acc[j]   = fma2(f0.y, w4.y, acc[j]);
            acc[9+j] = fma2(f1.x, w4.x, acc[9+j]);
            acc[9+j] = fma2(f1.y, w4.y, acc[9+j]);
        }
    }
#pragma unroll
    for (int t = 0; t < 2; ++t)
#pragma unroll
        for (int j = 0; j < 9; ++j) {
            float lo, hi; upk2(acc[t*9+j], lo, hi);
            float s = lo + hi + b_sh[c0+j];
            g_H[(size_t)(tok0 + t0 + t)*144 + c0 + j] = fmaxf(s, 0.f);
        }
}

// =======================================================================
// K4c: F[tok][i] = LOG2E*(fc2_b[i] + sum_e fc2_w[i][e]*H[tok][e])
// =======================================================================
#define FB_HS 148
#define FB_WS 150
__global__ __launch_bounds__(512, 1) void fbig_kernel(
    const float* __restrict__ fc2_w, const float* __restrict__ fc2_b)
{
    extern __shared__ float fsm[];
    float* Hs = fsm;                    // [128][FB_HS]
    float* Ws = Hs + 128*FB_HS;         // [144][FB_WS]
    float* bs = Ws + 144*FB_WS;         // [144]

    const int tid  = threadIdx.x;
    const int tok0 = blockIdx.x * 128;

    for (int idx = tid; idx < 128*36; idx += 512) {
        int t = idx / 36, kq = idx % 36;
        *(float4*)&Hs[t*FB_HS + kq*4] =
            *(const float4*)&g_H[(size_t)(tok0+t)*144 + kq*4];
    }
    for (int idx = tid; idx < 144*72; idx += 512) {
        int c = idx / 72, kp = idx % 72;
        *(float2*)&Ws[c*FB_WS + kp*2] = *(const float2*)&fc2_w[c*144 + kp*2];
    }
    if (tid < 144) bs[tid] = fc2_b[tid];
    __syncthreads();

    const int tg = tid >> 4;
    const int cg = tid & 15;
    const int t0 = tg * 4;
    const int c0 = cg * 9;

    ull acc[36];
#pragma unroll
    for (int a = 0; a < 36; ++a) acc[a] = 0ull;

#pragma unroll 4
    for (int kp = 0; kp < 72; ++kp) {
        const int kk = kp*2;
        ull hv[4];
#pragma unroll
        for (int j = 0; j < 4; ++j) hv[j] = *(const ull*)&Hs[(t0+j)*FB_HS + kk];
#pragma unroll
        for (int c = 0; c < 9; ++c) {
            ull wv = *(const ull*)&Ws[(c0+c)*FB_WS + kk];
#pragma unroll
            for (int j = 0; j < 4; ++j)
                acc[j*9+c] = fma2(hv[j], wv, acc[j*9+c]);
        }
    }

#pragma unroll
    for (int j = 0; j < 4; ++j)
#pragma unroll
        for (int c = 0; c < 9; ++c) {
            float lo, hi; upk2(acc[j*9+c], lo, hi);
            g_F[(size_t)(tok0 + t0 + j)*144 + c0 + c] =
                LOG2E*(lo + hi + bs[c0+c]);
        }
}

// =======================================================================
// K4b: prep — gather per-(seg,chunk) K rows ([xm*L2E (16) | F (144)]) and Y
// =======================================================================
__global__ __launch_bounds__(256) void prep_kernel()
{
    const int chunk = blockIdx.x;
    const int seg   = blockIdx.y;
    const int n     = seg >> 2;
    const int tid   = threadIdx.x;

    __shared__ int tq_sh[144];
    if (tid < 144) tq_sh[tid] = g_perm[seg*LL + chunk*CHK + tid];
    __syncthreads();

    float* Kdst = &g_K[((size_t)(seg*64 + chunk))*144*160];
    for (int idx = tid; idx < 144*40; idx += 256) {
        int i = idx / 40, d4 = idx % 40;
        int tokg = n*LL + tq_sh[i];
        float4 v;
        if (d4 < 4) {
            v = *(const float4*)&g_xm[tokg*16 + d4*4];
            v.x *= LOG2E; v.y *= LOG2E; v.z *= LOG2E; v.w *= LOG2E;
        } else {
            v = *(const float4*)&g_F[(size_t)tokg*144 + (d4-4)*4];
        }
        *(float4*)&Kdst[i*160 + d4*4] = v;
    }
    float* Ydst = &g_Y[((size_t)(seg*64 + chunk))*144*64];
    for (int idx = tid; idx < 144*16; idx += 256) {
        int i = idx / 16, e4 = idx % 16;
        int tokg = n*LL + tq_sh[i];
        *(float4*)&Ydst[i*64 + e4*4] = *(const float4*)&g_ye[(size_t)tokg*64 + e4*4];
    }
}

// =======================================================================
// K5: attention v4b — identical to v4 except __launch_bounds__(576, 1):
// lifts the 56-reg cap (spill elimination). Occupancy 1 block/SM, 18 warps.
// =======================================================================
#define S_STR  148
#define KX_STR 18

__global__ __launch_bounds__(576, 1) void attn_kernel()
{
    extern __shared__ __align__(16) char smraw[];
    ull*   P2    = (ull*)smraw;                    // [48][144] dup pairs
    float* S     = (float*)(P2 + 48*144);          // [48][S_STR]
    float* Yt    = S  + 48*S_STR;                  // [48][64]
    float* Kxm   = Yt + 48*64;                     // [48][KX_STR]
    float* xe_sh = Kxm + 48*KX_STR;                // [144][16]
    float* Mt    = xe_sh + 144*16;                 // [4][144]
    float* alS   = Mt + 4*144;                     // [144]
    int*   tq_sh = (int*)(alS + 144);              // [144]

    const int cblk = blockIdx.x;
    const int h    = blockIdx.y;
    const int n    = blockIdx.z;
    const int seg  = n*4 + h;
    const int tid  = threadIdx.x;

    if (tid < 144) tq_sh[tid] = g_perm[seg*LL + cblk*CHK + tid];
    __syncthreads();
    for (int idx = tid; idx < 144*4; idx += 576) {
        int i = idx >> 2, c4 = idx & 3;
        int tokg = n*LL + tq_sh[i];
        *(float4*)&xe_sh[i*16 + c4*4] = *(const float4*)&g_xe[tokg*16 + c4*4];
    }

    const int kg = tid % 12;        // phase-A key group (4 keys)
    const int qg = tid / 12;        // phase-A query group (3 queries)
    const int q1 = tid % 144;       // phase-B1 query
    const int kg1 = tid / 144;      // phase-B1 key quarter (12 keys)
    const int qg2 = tid >> 4;       // phase-B2 query group (4 queries)
    const int eg2 = tid & 15;       // phase-B2 e group (4 floats)
    const int q0B = qg2 * 4;

    float m = -1e30f, l = 0.f;
    ull racc[8];
#pragma unroll
    for (int r = 0; r < 8; ++r) racc[r] = 0ull;

    for (int t = 0; t < 9; ++t) {
        const int dc = t / 3;
        const int cc = (cblk + (dc == 1 ? 63 : (dc == 2 ? 1 : 0))) & 63;
        const int jr0 = (t % 3) * 48;

        __syncthreads();
        {
            const float* Ksrc = &g_K[(((size_t)(seg*64 + cc))*144 + jr0)*160];
            for (int idx = tid; idx < 48*40; idx += 576) {
                int r = idx / 40, c = idx % 40;
                float4 v = *(const float4*)&Ksrc[r*160 + c*4];
                if (c < 4) {
                    float* d = &Kxm[r*KX_STR + c*4];
                    *(float2*)d     = make_float2(v.x, v.y);
                    *(float2*)(d+2) = make_float2(v.z, v.w);
                } else {
                    *(float4*)&S[r*S_STR + (c-4)*4] = v;
                }
            }
            const float* Ysrc = &g_Y[(((size_t)(seg*64 + cc))*144 + jr0)*64];
            for (int idx = tid; idx < 48*16; idx += 576) {
                int r = idx / 16, c = idx % 16;
                *(float4*)&Yt[r*64 + c*4] = *(const float4*)&Ysrc[r*64 + c*4];
            }
        }
        __syncthreads();

        // ---- phase A: 16-d dots, add into prefetched F logits ----
        {
            ull acc[12];
#pragma unroll
            for (int a = 0; a < 12; ++a) acc[a] = 0ull;
#pragma unroll
            for (int dd = 0; dd < 16; dd += 2) {
                ull qa = *(const ull*)&xe_sh[(3*qg+0)*16 + dd];
                ull qb = *(const ull*)&xe_sh[(3*qg+1)*16 + dd];
                ull qc = *(const ull*)&xe_sh[(3*qg+2)*16 + dd];
#pragma unroll
                for (int i = 0; i < 4; ++i) {
                    ull kv = *(const ull*)&Kxm[(kg + 12*i)*KX_STR + dd];
                    acc[0*4+i] = fma2(qa, kv, acc[0*4+i]);
                    acc[1*4+i] = fma2(qb, kv, acc[1*4+i]);
                    acc[2*4+i] = fma2(qc, kv, acc[2*4+i]);
                }
            }
#pragma unroll
            for (int j = 0; j < 3; ++j)
#pragma unroll
                for (int i = 0; i < 4; ++i) {
                    float lo, hi; upk2(acc[j*4+i], lo, hi);
                    S[(kg + 12*i)*S_STR + 3*qg + j] += lo + hi;
                }
        }
        __syncthreads();

        // ---- phase B1: tile max + P materialization + l quarters ----
        {
            float tm = -1e30f;
#pragma unroll
            for (int j = 0; j < 12; ++j)
                tm = fmaxf(tm, S[(kg1*12 + j)*S_STR + q1]);
            Mt[kg1*144 + q1] = tm;
        }
        __syncthreads();
        {
            float tmax = fmaxf(fmaxf(Mt[q1], Mt[144+q1]),
                               fmaxf(Mt[288+q1], Mt[432+q1]));
            float mn = fmaxf(m, tmax);
            float al = ex2f(m - mn);
            m = mn;
            l *= al;
            if (kg1 == 0) alS[q1] = al;
#pragma unroll
            for (int j = 0; j < 12; ++j) {
                int k = kg1*12 + j;
                float p = ex2f(S[k*S_STR + q1] - mn);
                l += p;
                P2[k*144 + q1] = pk2(p, p);
            }
        }
        __syncthreads();

        // ---- phase B2: register-tiled P.Y GEMM (4q x 4e per thread) ----
        {
            float a0 = alS[q0B], a1 = alS[q0B+1], a2 = alS[q0B+2], a3 = alS[q0B+3];
            racc[0] = mul2_(racc[0], pk2(a0,a0)); racc[1] = mul2_(racc[1], pk2(a0,a0));
            racc[2] = mul2_(racc[2], pk2(a1,a1)); racc[3] = mul2_(racc[3], pk2(a1,a1));
            racc[4] = mul2_(racc[4], pk2(a2,a2)); racc[5] = mul2_(racc[5], pk2(a2,a2));
            racc[6] = mul2_(racc[6], pk2(a3,a3)); racc[7] = mul2_(racc[7], pk2(a3,a3));
#pragma unroll 4
            for (int k = 0; k < 48; ++k) {
                ull p0 = P2[k*144 + q0B];
                ull p1 = P2[k*144 + q0B+1];
                ull pq2 = P2[k*144 + q0B+2];
                ull p3 = P2[k*144 + q0B+3];
                ulonglong2 yv = *(const ulonglong2*)&Yt[k*64 + eg2*4];
                racc[0] = fma2(p0,  yv.x, racc[0]); racc[1] = fma2(p0,  yv.y, racc[1]);
                racc[2] = fma2(p1,  yv.x, racc[2]); racc[3] = fma2(p1,  yv.y, racc[3]);
                racc[4] = fma2(pq2, yv.x, racc[4]); racc[5] = fma2(pq2, yv.y, racc[5]);
                racc[6] = fma2(p3,  yv.x, racc[6]); racc[7] = fma2(p3,  yv.y, racc[7]);
            }
        }
    }

    // ---- epilogue ----
    __syncthreads();
    Mt[kg1*144 + q1] = l;          // per-quarter l
    __syncthreads();
    if (tid < 144) {
        float lt = Mt[tid] + Mt[144+tid] + Mt[288+tid] + Mt[432+tid];
        alS[tid] = 1.f / lt;       // reuse alS as inv-l
        g_bsc[seg*LL + tq_sh[tid]] = (m + lg2f(lt)) * LN2;  // tid==q1, kg1==0 holds m
    }
    __syncthreads();
    {
        float i0 = alS[q0B], i1 = alS[q0B+1], i2 = alS[q0B+2], i3 = alS[q0B+3];
        ull iv0 = pk2(i0,i0), iv1 = pk2(i1,i1), iv2 = pk2(i2,i2), iv3 = pk2(i3,i3);
        const int ebase = eg2*4;
#pragma unroll
        for (int j = 0; j < 4; ++j) {
            ull ivj = (j==0) ? iv0 : (j==1) ? iv1 : (j==2) ? iv2 : iv3;
            int tq = tq_sh[q0B + j];
            ulonglong2 o;
            o.x = mul2_(racc[2*j],   ivj);
            o.y = mul2_(racc[2*j+1], ivj);
            *(ulonglong2*)&g_ret[((size_t)seg*LL + tq)*64 + ebase] = o;
        }
    }
}

// =======================================================================
// K6: per-token softmax over heads + residual, NCHW output
// =======================================================================
__global__ __launch_bounds__(256) void final_kernel(
    const float* __restrict__ x, float* __restrict__ out)
{
    const int tg = blockIdx.x*256 + threadIdx.x;
    const int n = tg / LL, tt = tg % LL;
    float b[4];
    float mx = -1e30f;
#pragma unroll
    for (int h = 0; h < 4; ++h) {
        b[h] = g_bsc[(n*4+h)*LL + tt];
        mx = fmaxf(mx, b[h]);
    }
    float wsum = 0.f;
#pragma unroll
    for (int h = 0; h < 4; ++h) { b[h] = __expf(b[h] - mx); wsum += b[h]; }
    const float inv = 1.f / wsum;
#pragma unroll
    for (int c4 = 0; c4 < 16; ++c4) {
        float4 acc = {0.f, 0.f, 0.f, 0.f};
#pragma unroll
        for (int h = 0; h < 4; ++h) {
            float4 r = *(const float4*)&g_ret[((size_t)(n*4+h)*LL + tt)*64 + c4*4];
            float wv = b[h]*inv;
            acc.x += wv*r.x; acc.y += wv*r.y; acc.z += wv*r.z; acc.w += wv*r.w;
        }
        int c = c4*4;
        out[(n*64+c  )*LL + tt] = acc.x + x[(n*64+c  )*LL + tt];
        out[(n*64+c+1)*LL + tt] = acc.y + x[(n*64+c+1)*LL + tt];
        out[(n*64+c+2)*LL + tt] = acc.z + x[(n*64+c+2)*LL + tt];
        out[(n*64+c+3)*LL + tt] = acc.w + x[(n*64+c+3)*LL + tt];
    }
}

// =======================================================================
extern "C" void kernel_launch(void* const* d_in, const int* in_sizes, int n_in,
                              void* d_out, int out_size)
{
    const float* x     = (const float*)d_in[0];
    const float* rot   = (const float*)d_in[1];
    const float* wm    = (const float*)d_in[2];
    const float* bm    = (const float*)d_in[3];
    const float* wa    = (const float*)d_in[4];
    const float* ba    = (const float*)d_in[5];
    const float* wf    = (const float*)d_in[6];
    const float* bf    = (const float*)d_in[7];
    const float* fc1_w = (const float*)d_in[8];
    const float* fc1_b = (const float*)d_in[9];
    const float* fc2_w = (const float*)d_in[10];
    const float* fc2_b = (const float*)d_in[11];
    float* out = (float*)d_out;

    const int attn_smem = 48*144*8
        + (48*S_STR + 48*64 + 48*KX_STR + 144*16 + 4*144 + 144) * 4
        + 144*4;
    const int fbig_smem = (128*FB_HS + 144*FB_WS + 144) * 4;
    cudaFuncSetAttribute(attn_kernel,
                         cudaFuncAttributeMaxDynamicSharedMemorySize, attn_smem);
    cudaFuncSetAttribute(fbig_kernel,
                         cudaFuncAttributeMaxDynamicSharedMemorySize, fbig_smem);

    conv_kernel <<<dim3(96, 2, 2), dim3(96, 3)>>>(x, wm, bm, wa, ba, wf, bf);
    code_kernel <<<72, 256>>>(rot);
    sort_kernel <<<8, 256>>>();
    hid_kernel  <<<576, 256>>>(fc1_w, fc1_b);
    fbig_kernel <<<144, 512, fbig_smem>>>(fc2_w, fc2_b);
    prep_kernel <<<dim3(64, 8), 256>>>();
    attn_kernel <<<dim3(64, 4, 2), 576, attn_smem>>>();
    final_kernel<<<72, 256>>>(x, out);
}

// round 14
// speedup vs baseline: 1.0441x; 1.0441x over previous
#include <cuda_runtime.h>
#include <math.h>

#define NB 2
#define LL 9216
#define NHH 4
#define CHK 144
#define NCHK 64
#define TOKS (NB*LL)

// ---------------- static scratch ----------------
__device__ float g_xe[TOKS*16];
__device__ float g_xm[TOKS*16];
__device__ float g_ye[(size_t)TOKS*64];
__device__ float g_fe[(size_t)TOKS*64];
__device__ float g_F [(size_t)TOKS*144];
__device__ unsigned char g_code[NB*NHH*LL];
__device__ int   g_perm[NB*NHH*LL];
__device__ float g_bsc[NB*NHH*LL];
__device__ float g_ret[(size_t)NB*NHH*LL*64];
// pre-gathered per-(seg,chunk) K rows ([xm*L2E (16) | F (144)]) and Y rows
__device__ float g_K[(size_t)8*64*144*160];
__device__ float g_Y[(size_t)8*64*144*64];

// ---------------- packed f32x2 helpers ----------------
typedef unsigned long long ull;
__device__ __forceinline__ ull pk2(float a, float b) {
    ull r; asm("mov.b64 %0,{%1,%2};" : "=l"(r) : "f"(a), "f"(b)); return r;
}
__device__ __forceinline__ void upk2(ull v, float& a, float& b) {
    asm("mov.b64 {%0,%1},%2;" : "=f"(a), "=f"(b) : "l"(v));
}
__device__ __forceinline__ ull fma2(ull a, ull b, ull c) {
    ull d; asm("fma.rn.f32x2 %0,%1,%2,%3;" : "=l"(d) : "l"(a), "l"(b), "l"(c)); return d;
}
__device__ __forceinline__ ull mul2_(ull a, ull b) {
    ull d; asm("mul.rn.f32x2 %0,%1,%2;" : "=l"(d) : "l"(a), "l"(b)); return d;
}
__device__ __forceinline__ float ex2f(float x) {
    float y; asm("ex2.approx.ftz.f32 %0,%1;" : "=f"(y) : "f"(x)); return y;
}
__device__ __forceinline__ float lg2f(float x) {
    float y; asm("lg2.approx.ftz.f32 %0,%1;" : "=f"(y) : "f"(x)); return y;
}
#define LOG2E 1.4426950408889634f
#define LN2   0.6931471805599453f

// =======================================================================
// K1: fused 3x3 SAME conv (144 out ch) + ReLU -> xe(16), ye(64), fe(64)
// =======================================================================
__global__ __launch_bounds__(288) void conv_kernel(
    const float* __restrict__ x,
    const float* __restrict__ wm, const float* __restrict__ bm,
    const float* __restrict__ wa, const float* __restrict__ ba,
    const float* __restrict__ wf, const float* __restrict__ bf)
{
    __shared__ float in_sh[8][3][100];
    __shared__ __align__(16) float w_sh[8][9][72];

    const int y    = blockIdx.x;
    const int n    = blockIdx.y;
    const int half = blockIdx.z;
    const int xcol = threadIdx.x;
    const int lane = threadIdx.y;
    const int tid  = xcol + 96*lane;
    const int coBase = half*72;

    ull acc2[12];
#pragma unroll
    for (int m = 0; m < 12; ++m) acc2[m] = 0ull;

    for (int cb = 0; cb < 8; ++cb) {
        __syncthreads();
        for (int idx = tid; idx < 8*3*98; idx += 288) {
            int c = idx / 294, rem = idx % 294, r = rem / 98, xx = rem % 98;
            int gy = y - 1 + r, gx = xx - 1, ci = cb*8 + c;
            float v = 0.f;
            if (gy >= 0 && gy < 96 && gx >= 0 && gx < 96)
                v = x[((n*64 + ci)*96 + gy)*96 + gx];
            in_sh[c][r][xx] = v;
        }
        for (int idx = tid; idx < 8*72*9; idx += 288) {
            int c = idx / 648, rem = idx % 648, tap = rem / 72, co_l = rem % 72;
            int co = coBase + co_l, ci = cb*8 + c;
            float w;
            if (co < 16)      w = wm[( co      *64 + ci)*9 + tap];
            else if (co < 80) w = wa[((co-16)*64 + ci)*9 + tap];
            else              w = wf[((co-80)*64 + ci)*9 + tap];
            w_sh[c][tap][co_l] = w;
        }
        __syncthreads();
#pragma unroll
        for (int c = 0; c < 8; ++c) {
            ull d[9];
            d[0] = pk2(in_sh[c][0][xcol],   in_sh[c][0][xcol]);
            d[1] = pk2(in_sh[c][0][xcol+1], in_sh[c][0][xcol+1]);
            d[2] = pk2(in_sh[c][0][xcol+2], in_sh[c][0][xcol+2]);
            d[3] = pk2(in_sh[c][1][xcol],   in_sh[c][1][xcol]);
            d[4] = pk2(in_sh[c][1][xcol+1], in_sh[c][1][xcol+1]);
            d[5] = pk2(in_sh[c][1][xcol+2], in_sh[c][1][xcol+2]);
            d[6] = pk2(in_sh[c][2][xcol],   in_sh[c][2][xcol]);
            d[7] = pk2(in_sh[c][2][xcol+1], in_sh[c][2][xcol+1]);
            d[8] = pk2(in_sh[c][2][xcol+2], in_sh[c][2][xcol+2]);
#pragma unroll
            for (int tap = 0; tap < 9; ++tap) {
                const ulonglong2* wp = (const ulonglong2*)&w_sh[c][tap][lane*24];
#pragma unroll
                for (int v = 0; v < 6; ++v) {
                    ulonglong2 w4 = wp[v];
                    acc2[2*v]   = fma2(d[tap], w4.x, acc2[2*v]);
                    acc2[2*v+1] = fma2(d[tap], w4.y, acc2[2*v+1]);
                }
            }
        }
    }

    const int tok = n*LL + y*96 + xcol;
    float acc[24];
#pragma unroll
    for (int m = 0; m < 12; ++m) upk2(acc2[m], acc[2*m], acc[2*m+1]);
#pragma unroll
    for (int m = 0; m < 24; ++m) {
        int co = coBase + lane*24 + m;
        if (co < 16) {
            g_xe[tok*16 + co] = fmaxf(acc[m] + bm[co], 0.f);
        } else if (co < 80) {
            g_ye[(size_t)tok*64 + (co-16)] = fmaxf(acc[m] + ba[co-16], 0.f);
        } else {
            g_fe[(size_t)tok*64 + (co-80)] = fmaxf(acc[m] + bf[co-80], 0.f);
        }
    }
}

// =======================================================================
// K2: LSH codes + normalized xm
// =======================================================================
__global__ __launch_bounds__(256) void code_kernel(const float* __restrict__ rot)
{
    __shared__ __align__(16) float rotT[4096];
    const int tid = threadIdx.x;
    for (int idx = tid; idx < 4096; idx += 256) {
        int hi = idx >> 4, f = idx & 15;
        rotT[idx] = rot[f*256 + hi];
    }
    __syncthreads();

    const int tg = blockIdx.x*256 + tid;
    const int n = tg / LL, t = tg % LL;

    const ulonglong2* ep = (const ulonglong2*)&g_xe[tg*16];
    ull ev[8];
#pragma unroll
    for (int i = 0; i < 4; ++i) { ulonglong2 v = ep[i]; ev[2*i] = v.x; ev[2*i+1] = v.y; }

    ull ssp = 0ull;
#pragma unroll
    for (int i = 0; i < 8; ++i) ssp = fma2(ev[i], ev[i], ssp);
    float slo, shi; upk2(ssp, slo, shi);
    float inv = 1.f / fmaxf(sqrtf(slo + shi), 5e-5f);
    ull invd = pk2(inv, inv);
    ulonglong2* xmp = (ulonglong2*)&g_xm[tg*16];
#pragma unroll
    for (int i = 0; i < 4; ++i) {
        ulonglong2 o;
        o.x = mul2_(ev[2*i], invd); o.y = mul2_(ev[2*i+1], invd);
        xmp[i] = o;
    }

#pragma unroll
    for (int h = 0; h < 4; ++h) {
        float best = -1e30f; int bi = 0;
        for (int i = 0; i < 64; ++i) {
            const ull* rr = (const ull*)&rotT[(h*64+i)*16];
            ull sp = 0ull;
#pragma unroll
            for (int j = 0; j < 8; ++j) sp = fma2(ev[j], rr[j], sp);
            float a, b; upk2(sp, a, b);
            float dd = a + b;
            if (dd > best) { best = dd; bi = i; }
        }
        g_code[(n*4+h)*LL + t] = (unsigned char)bi;
    }
}

// =======================================================================
// K3: per-(n,h) stable counting sort over 64 buckets -> g_perm
// =======================================================================
__global__ __launch_bounds__(256) void sort_kernel()
{
    const int seg = blockIdx.x;
    __shared__ int hist[64];
    __shared__ int running[64];
    __shared__ int wh[8][64];
    const int tid = threadIdx.x;
    const int w = tid >> 5, ln = tid & 31;

    if (tid < 64) hist[tid] = 0;
    __syncthreads();
    const unsigned char* code = &g_code[seg*LL];
    for (int t = tid; t < LL; t += 256) atomicAdd(&hist[code[t]], 1);
    __syncthreads();
    if (tid == 0) {
        int acc = 0;
        for (int b = 0; b < 64; ++b) { running[b] = acc; acc += hist[b]; }
    }
    __syncthreads();

    for (int tile = 0; tile < 36; ++tile) {
        int t = tile*256 + tid;
        int c = code[t];
        unsigned mask = __match_any_sync(0xffffffffu, c);
        int lanerank = __popc(mask & ((1u << ln) - 1u));
        ((int*)wh)[tid] = 0; ((int*)wh)[tid + 256] = 0;
        __syncthreads();
        if (lanerank == 0) wh[w][c] = __popc(mask);
        __syncthreads();
        int r = lanerank;
        for (int w2 = 0; w2 < w; ++w2) r += wh[w2][c];
        int pos = running[c] + r;
        __syncthreads();
        if (tid < 64) {
            int s = 0;
            for (int w2 = 0; w2 < 8; ++w2) s += wh[w2][tid];
            running[tid] += s;
        }
        __syncthreads();
        g_perm[seg*LL + pos] = t;
    }
}

// =======================================================================
// K4: fused hid+fbig. Per 32-token block:
//   H[t][c] = relu(fe[t] . fc1_w[c] + fc1_b[c])       (into smem)
//   F[t][c] = LOG2E*(fc2_b[c] + sum_e fc2_w[c][e]*H[t][e])  (to gmem)
// =======================================================================
#define HF_HS 146
#define HF_WS 146
__global__ __launch_bounds__(256, 1) void hidf_kernel(
    const float* __restrict__ fc1_w, const float* __restrict__ fc1_b,
    const float* __restrict__ fc2_w, const float* __restrict__ fc2_b)
{
    extern __shared__ __align__(16) float hsm[];
    float* w1_sh = hsm;                    // [144][68]
    float* fe_sh = w1_sh + 144*68;         // [32][68]
    float* w2_sh = fe_sh + 32*68;          // [144][HF_WS]
    float* H_sh  = w2_sh + 144*HF_WS;      // [32][HF_HS]
    float* b1_sh = H_sh + 32*HF_HS;        // [144]
    float* b2_sh = b1_sh + 144;            // [144]

    const int tid = threadIdx.x;
    const int tok0 = blockIdx.x * 32;

    for (int idx = tid; idx < 144*16; idx += 256) {
        int col = idx >> 4, kq = idx & 15;
        *(float4*)&w1_sh[col*68 + kq*4] = *(const float4*)&fc1_w[col*64 + kq*4];
    }
    for (int idx = tid; idx < 32*16; idx += 256) {
        int t = idx >> 4, kq = idx & 15;
        *(float4*)&fe_sh[t*68 + kq*4] = *(const float4*)&g_fe[(size_t)(tok0+t)*64 + kq*4];
    }
    for (int idx = tid; idx < 144*72; idx += 256) {
        int c = idx / 72, kp = idx % 72;
        *(float2*)&w2_sh[c*HF_WS + kp*2] = *(const float2*)&fc2_w[c*144 + kp*2];
    }
    if (tid < 144) { b1_sh[tid] = fc1_b[tid]; b2_sh[tid] = fc2_b[tid]; }
    __syncthreads();

    const int cg = tid & 15;       // 9 cols each
    const int tg = tid >> 4;       // 2 tokens each
    const int c0 = cg * 9;
    const int t0 = tg * 2;

    // ---- phase 1: H ----
    {
        ull acc[18];
#pragma unroll
        for (int j = 0; j < 18; ++j) acc[j] = 0ull;
#pragma unroll
        for (int kk = 0; kk < 16; ++kk) {
            ulonglong2 f0 = *(const ulonglong2*)&fe_sh[t0*68 + kk*4];
            ulonglong2 f1 = *(const ulonglong2*)&fe_sh[(t0+1)*68 + kk*4];
#pragma unroll
            for (int j = 0; j < 9; ++j) {
                ulonglong2 w4 = *(const ulonglong2*)&w1_sh[(c0+j)*68 + kk*4];
                acc[j]   = fma2(f0.x, w4.x, acc[j]);
                acc[j]   = fma2(f0.y, w4.y, acc[j]);
                acc[9+j] = fma2(f1.x, w4.x, acc[9+j]);
                acc[9+j] = fma2(f1.y, w4.y, acc[9+j]);
            }
        }
#pragma unroll
        for (int t = 0; t < 2; ++t)
#pragma unroll
            for (int j = 0; j < 9; ++j) {
                float lo, hi; upk2(acc[t*9+j], lo, hi);
                float s = lo + hi + b1_sh[c0+j];
                H_sh[(t0+t)*HF_HS + c0 + j] = fmaxf(s, 0.f);
            }
    }
    __syncthreads();

    // ---- phase 2: F = LOG2E*(fc2_b + H . fc2_w^T) ----
    {
        ull acc[18];
#pragma unroll
        for (int j = 0; j < 18; ++j) acc[j] = 0ull;
#pragma unroll 8
        for (int kp = 0; kp < 72; ++kp) {
            const int kk = kp*2;
            ull h0 = *(const ull*)&H_sh[t0*HF_HS + kk];
            ull h1 = *(const ull*)&H_sh[(t0+1)*HF_HS + kk];
#pragma unroll
            for (int j = 0; j < 9; ++j) {
                ull wv = *(const ull*)&w2_sh[(c0+j)*HF_WS + kk];
                acc[j]   = fma2(h0, wv, acc[j]);
                acc[9+j] = fma2(h1, wv, acc[9+j]);
            }
        }
#pragma unroll
        for (int t = 0; t < 2; ++t)
#pragma unroll
            for (int j = 0; j < 9; ++j) {
                float lo, hi; upk2(acc[t*9+j], lo, hi);
                g_F[(size_t)(tok0 + t0 + t)*144 + c0 + j] =
                    LOG2E*(lo + hi + b2_sh[c0+j]);
            }
    }
}

// =======================================================================
// K4b: prep — gather per-(seg,chunk) K rows ([xm*L2E (16) | F (144)]) and Y
// =======================================================================
__global__ __launch_bounds__(256) void prep_kernel()
{
    const int chunk = blockIdx.x;
    const int seg   = blockIdx.y;
    const int n     = seg >> 2;
    const int tid   = threadIdx.x;

    __shared__ int tq_sh[144];
    if (tid < 144) tq_sh[tid] = g_perm[seg*LL + chunk*CHK + tid];
    __syncthreads();

    float* Kdst = &g_K[((size_t)(seg*64 + chunk))*144*160];
    for (int idx = tid; idx < 144*40; idx += 256) {
        int i = idx / 40, d4 = idx % 40;
        int tokg = n*LL + tq_sh[i];
        float4 v;
        if (d4 < 4) {
            v = *(const float4*)&g_xm[tokg*16 + d4*4];
            v.x *= LOG2E; v.y *= LOG2E; v.z *= LOG2E; v.w *= LOG2E;
        } else {
            v = *(const float4*)&g_F[(size_t)tokg*144 + (d4-4)*4];
        }
        *(float4*)&Kdst[i*160 + d4*4] = v;
    }
    float* Ydst = &g_Y[((size_t)(seg*64 + chunk))*144*64];
    for (int idx = tid; idx < 144*16; idx += 256) {
        int i = idx / 16, e4 = idx % 16;
        int tokg = n*LL + tq_sh[i];
        *(float4*)&Ydst[i*64 + e4*4] = *(const float4*)&g_ye[(size_t)tokg*64 + e4*4];
    }
}

// =======================================================================
// K5: attention v4 (R12 best) — per (n,h,chunk), 576 threads, 2 blocks/SM.
// =======================================================================
#define S_STR  148
#define KX_STR 18

__global__ __launch_bounds__(576, 2) void attn_kernel()
{
    extern __shared__ __align__(16) char smraw[];
    ull*   P2    = (ull*)smraw;                    // [48][144] dup pairs
    float* S     = (float*)(P2 + 48*144);          // [48][S_STR]
    float* Yt    = S  + 48*S_STR;                  // [48][64]
    float* Kxm   = Yt + 48*64;                     // [48][KX_STR]
    float* xe_sh = Kxm + 48*KX_STR;                // [144][16]
    float* Mt    = xe_sh + 144*16;                 // [4][144]
    float* alS   = Mt + 4*144;                     // [144]
    int*   tq_sh = (int*)(alS + 144);              // [144]

    const int cblk = blockIdx.x;
    const int h    = blockIdx.y;
    const int n    = blockIdx.z;
    const int seg  = n*4 + h;
    const int tid  = threadIdx.x;

    if (tid < 144) tq_sh[tid] = g_perm[seg*LL + cblk*CHK + tid];
    __syncthreads();
    for (int idx = tid; idx < 144*4; idx += 576) {
        int i = idx >> 2, c4 = idx & 3;
        int tokg = n*LL + tq_sh[i];
        *(float4*)&xe_sh[i*16 + c4*4] = *(const float4*)&g_xe[tokg*16 + c4*4];
    }

    const int kg = tid % 12;        // phase-A key group (4 keys)
    const int qg = tid / 12;        // phase-A query group (3 queries)
    const int q1 = tid % 144;       // phase-B1 query
    const int kg1 = tid / 144;      // phase-B1 key quarter (12 keys)
    const int qg2 = tid >> 4;       // phase-B2 query group (4 queries)
    const int eg2 = tid & 15;       // phase-B2 e group (4 floats)
    const int q0B = qg2 * 4;

    float m = -1e30f, l = 0.f;
    ull racc[8];
#pragma unroll
    for (int r = 0; r < 8; ++r) racc[r] = 0ull;

    for (int t = 0; t < 9; ++t) {
        const int dc = t / 3;
        const int cc = (cblk + (dc == 1 ? 63 : (dc == 2 ? 1 : 0))) & 63;
        const int jr0 = (t % 3) * 48;

        __syncthreads();
        {
            const float* Ksrc = &g_K[(((size_t)(seg*64 + cc))*144 + jr0)*160];
            for (int idx = tid; idx < 48*40; idx += 576) {
                int r = idx / 40, c = idx % 40;
                float4 v = *(const float4*)&Ksrc[r*160 + c*4];
                if (c < 4) {
                    float* d = &Kxm[r*KX_STR + c*4];
                    *(float2*)d     = make_float2(v.x, v.y);
                    *(float2*)(d+2) = make_float2(v.z, v.w);
                } else {
                    *(float4*)&S[r*S_STR + (c-4)*4] = v;
                }
            }
            const float* Ysrc = &g_Y[(((size_t)(seg*64 + cc))*144 + jr0)*64];
            for (int idx = tid; idx < 48*16; idx += 576) {
                int r = idx / 16, c = idx % 16;
                *(float4*)&Yt[r*64 + c*4] = *(const float4*)&Ysrc[r*64 + c*4];
            }
        }
        __syncthreads();

        // ---- phase A: 16-d dots, add into prefetched F logits ----
        {
            ull acc[12];
#pragma unroll
            for (int a = 0; a < 12; ++a) acc[a] = 0ull;
#pragma unroll
            for (int dd = 0; dd < 16; dd += 2) {
                ull qa = *(const ull*)&xe_sh[(3*qg+0)*16 + dd];
                ull qb = *(const ull*)&xe_sh[(3*qg+1)*16 + dd];
                ull qc = *(const ull*)&xe_sh[(3*qg+2)*16 + dd];
#pragma unroll
                for (int i = 0; i < 4; ++i) {
                    ull kv = *(const ull*)&Kxm[(kg + 12*i)*KX_STR + dd];
                    acc[0*4+i] = fma2(qa, kv, acc[0*4+i]);
                    acc[1*4+i] = fma2(qb, kv, acc[1*4+i]);
                    acc[2*4+i] = fma2(qc, kv, acc[2*4+i]);
                }
            }
#pragma unroll
            for (int j = 0; j < 3; ++j)
#pragma unroll
                for (int i = 0; i < 4; ++i) {
                    float lo, hi; upk2(acc[j*4+i], lo, hi);
                    S[(kg + 12*i)*S_STR + 3*qg + j] += lo + hi;
                }
        }
        __syncthreads();

        // ---- phase B1: tile max + P materialization + l quarters ----
        {
            float tm = -1e30f;
#pragma unroll
            for (int j = 0; j < 12; ++j)
                tm = fmaxf(tm, S[(kg1*12 + j)*S_STR + q1]);
            Mt[kg1*144 + q1] = tm;
        }
        __syncthreads();
        {
            float tmax = fmaxf(fmaxf(Mt[q1], Mt[144+q1]),
                               fmaxf(Mt[288+q1], Mt[432+q1]));
            float mn = fmaxf(m, tmax);
            float al = ex2f(m - mn);
            m = mn;
            l *= al;
            if (kg1 == 0) alS[q1] = al;
#pragma unroll
            for (int j = 0; j < 12; ++j) {
                int k = kg1*12 + j;
                float p = ex2f(S[k*S_STR + q1] - mn);
                l += p;
                P2[k*144 + q1] = pk2(p, p);
            }
        }
        __syncthreads();

        // ---- phase B2: register-tiled P.Y GEMM (4q x 4e per thread) ----
        {
            float a0 = alS[q0B], a1 = alS[q0B+1], a2 = alS[q0B+2], a3 = alS[q0B+3];
            racc[0] = mul2_(racc[0], pk2(a0,a0)); racc[1] = mul2_(racc[1], pk2(a0,a0));
            racc[2] = mul2_(racc[2], pk2(a1,a1)); racc[3] = mul2_(racc[3], pk2(a1,a1));
            racc[4] = mul2_(racc[4], pk2(a2,a2)); racc[5] = mul2_(racc[5], pk2(a2,a2));
            racc[6] = mul2_(racc[6], pk2(a3,a3)); racc[7] = mul2_(racc[7], pk2(a3,a3));
#pragma unroll 4
            for (int k = 0; k < 48; ++k) {
                ull p0 = P2[k*144 + q0B];
                ull p1 = P2[k*144 + q0B+1];
                ull pq2 = P2[k*144 + q0B+2];
                ull p3 = P2[k*144 + q0B+3];
                ulonglong2 yv = *(const ulonglong2*)&Yt[k*64 + eg2*4];
                racc[0] = fma2(p0,  yv.x, racc[0]); racc[1] = fma2(p0,  yv.y, racc[1]);
                racc[2] = fma2(p1,  yv.x, racc[2]); racc[3] = fma2(p1,  yv.y, racc[3]);
                racc[4] = fma2(pq2, yv.x, racc[4]); racc[5] = fma2(pq2, yv.y, racc[5]);
                racc[6] = fma2(p3,  yv.x, racc[6]); racc[7] = fma2(p3,  yv.y, racc[7]);
            }
        }
    }

    // ---- epilogue ----
    __syncthreads();
    Mt[kg1*144 + q1] = l;          // per-quarter l
    __syncthreads();
    if (tid < 144) {
        float lt = Mt[tid] + Mt[144+tid] + Mt[288+tid] + Mt[432+tid];
        alS[tid] = 1.f / lt;       // reuse alS as inv-l
        g_bsc[seg*LL + tq_sh[tid]] = (m + lg2f(lt)) * LN2;  // tid==q1, kg1==0 holds m
    }
    __syncthreads();
    {
        float i0 = alS[q0B], i1 = alS[q0B+1], i2 = alS[q0B+2], i3 = alS[q0B+3];
        ull iv0 = pk2(i0,i0), iv1 = pk2(i1,i1), iv2 = pk2(i2,i2), iv3 = pk2(i3,i3);
        const int ebase = eg2*4;
#pragma unroll
        for (int j = 0; j < 4; ++j) {
            ull ivj = (j==0) ? iv0 : (j==1) ? iv1 : (j==2) ? iv2 : iv3;
            int tq = tq_sh[q0B + j];
            ulonglong2 o;
            o.x = mul2_(racc[2*j],   ivj);
            o.y = mul2_(racc[2*j+1], ivj);
            *(ulonglong2*)&g_ret[((size_t)seg*LL + tq)*64 + ebase] = o;
        }
    }
}

// =======================================================================
// K6: per-token softmax over heads + residual, NCHW output
// =======================================================================
__global__ __launch_bounds__(256) void final_kernel(
    const float* __restrict__ x, float* __restrict__ out)
{
    const int tg = blockIdx.x*256 + threadIdx.x;
    const int n = tg / LL, tt = tg % LL;
    float b[4];
    float mx = -1e30f;
#pragma unroll
    for (int h = 0; h < 4; ++h) {
        b[h] = g_bsc[(n*4+h)*LL + tt];
        mx = fmaxf(mx, b[h]);
    }
    float wsum = 0.f;
#pragma unroll
    for (int h = 0; h < 4; ++h) { b[h] = __expf(b[h] - mx); wsum += b[h]; }
    const float inv = 1.f / wsum;
#pragma unroll
    for (int c4 = 0; c4 < 16; ++c4) {
        float4 acc = {0.f, 0.f, 0.f, 0.f};
#pragma unroll
        for (int h = 0; h < 4; ++h) {
            float4 r = *(const float4*)&g_ret[((size_t)(n*4+h)*LL + tt)*64 + c4*4];
            float wv = b[h]*inv;
            acc.x += wv*r.x; acc.y += wv*r.y; acc.z += wv*r.z; acc.w += wv*r.w;
        }
        int c = c4*4;
        out[(n*64+c  )*LL + tt] = acc.x + x[(n*64+c  )*LL + tt];
        out[(n*64+c+1)*LL + tt] = acc.y + x[(n*64+c+1)*LL + tt];
        out[(n*64+c+2)*LL + tt] = acc.z + x[(n*64+c+2)*LL + tt];
        out[(n*64+c+3)*LL + tt] = acc.w + x[(n*64+c+3)*LL + tt];
    }
}

// =======================================================================
extern "C" void kernel_launch(void* const* d_in, const int* in_sizes, int n_in,
                              void* d_out, int out_size)
{
    const float* x     = (const float*)d_in[0];
    const float* rot   = (const float*)d_in[1];
    const float* wm    = (const float*)d_in[2];
    const float* bm    = (const float*)d_in[3];
    const float* wa    = (const float*)d_in[4];
    const float* ba    = (const float*)d_in[5];
    const float* wf    = (const float*)d_in[6];
    const float* bf    = (const float*)d_in[7];
    const float* fc1_w = (const float*)d_in[8];
    const float* fc1_b = (const float*)d_in[9];
    const float* fc2_w = (const float*)d_in[10];
    const float* fc2_b = (const float*)d_in[11];
    float* out = (float*)d_out;

    const int attn_smem = 48*144*8
        + (48*S_STR + 48*64 + 48*KX_STR + 144*16 + 4*144 + 144) * 4
        + 144*4;
    const int hidf_smem = (144*68 + 32*68 + 144*HF_WS + 32*HF_HS + 288) * 4;
    cudaFuncSetAttribute(attn_kernel,
                         cudaFuncAttributeMaxDynamicSharedMemorySize, attn_smem);
    cudaFuncSetAttribute(hidf_kernel,
                         cudaFuncAttributeMaxDynamicSharedMemorySize, hidf_smem);

    conv_kernel <<<dim3(96, 2, 2), dim3(96, 3)>>>(x, wm, bm, wa, ba, wf, bf);
    code_kernel <<<72, 256>>>(rot);
    sort_kernel <<<8, 256>>>();
    hidf_kernel <<<576, 256, hidf_smem>>>(fc1_w, fc1_b, fc2_w, fc2_b);
    prep_kernel <<<dim3(64, 8), 256>>>();
    attn_kernel <<<dim3(64, 4, 2), 576, attn_smem>>>();
    final_kernel<<<72, 256>>>(x, out);
}

// round 15
// speedup vs baseline: 1.1083x; 1.0615x over previous
#include <cuda_runtime.h>
#include <math.h>

#define NB 2
#define LL 9216
#define NHH 4
#define CHK 144
#define NCHK 64
#define TOKS (NB*LL)

// ---------------- static scratch ----------------
__device__ float g_xe[TOKS*16];
__device__ float g_xm[TOKS*16];
__device__ float g_ye[(size_t)TOKS*64];
__device__ float g_fe[(size_t)TOKS*64];
__device__ float g_H [(size_t)TOKS*144];
__device__ float g_F [(size_t)TOKS*144];
__device__ unsigned char g_code[NB*NHH*LL];
__device__ int   g_perm[NB*NHH*LL];
__device__ float g_bsc[NB*NHH*LL];
__device__ float g_ret[(size_t)NB*NHH*LL*64];

// ---------------- packed f32x2 helpers ----------------
typedef unsigned long long ull;
__device__ __forceinline__ ull pk2(float a, float b) {
    ull r; asm("mov.b64 %0,{%1,%2};" : "=l"(r) : "f"(a), "f"(b)); return r;
}
__device__ __forceinline__ void upk2(ull v, float& a, float& b) {
    asm("mov.b64 {%0,%1},%2;" : "=f"(a), "=f"(b) : "l"(v));
}
__device__ __forceinline__ ull fma2(ull a, ull b, ull c) {
    ull d; asm("fma.rn.f32x2 %0,%1,%2,%3;" : "=l"(d) : "l"(a), "l"(b), "l"(c)); return d;
}
__device__ __forceinline__ ull mul2_(ull a, ull b) {
    ull d; asm("mul.rn.f32x2 %0,%1,%2;" : "=l"(d) : "l"(a), "l"(b)); return d;
}
__device__ __forceinline__ float ex2f(float x) {
    float y; asm("ex2.approx.ftz.f32 %0,%1;" : "=f"(y) : "f"(x)); return y;
}
__device__ __forceinline__ float lg2f(float x) {
    float y; asm("lg2.approx.ftz.f32 %0,%1;" : "=f"(y) : "f"(x)); return y;
}
#define LOG2E 1.4426950408889634f
#define LN2   0.6931471805599453f

// =======================================================================
// K1: fused 3x3 SAME conv (144 out ch) + ReLU -> xe(16), ye(64), fe(64)
// =======================================================================
__global__ __launch_bounds__(288) void conv_kernel(
    const float* __restrict__ x,
    const float* __restrict__ wm, const float* __restrict__ bm,
    const float* __restrict__ wa, const float* __restrict__ ba,
    const float* __restrict__ wf, const float* __restrict__ bf)
{
    __shared__ float in_sh[8][3][100];
    __shared__ __align__(16) float w_sh[8][9][72];

    const int y    = blockIdx.x;
    const int n    = blockIdx.y;
    const int half = blockIdx.z;
    const int xcol = threadIdx.x;
    const int lane = threadIdx.y;
    const int tid  = xcol + 96*lane;
    const int coBase = half*72;

    ull acc2[12];
#pragma unroll
    for (int m = 0; m < 12; ++m) acc2[m] = 0ull;

    for (int cb = 0; cb < 8; ++cb) {
        __syncthreads();
        for (int idx = tid; idx < 8*3*98; idx += 288) {
            int c = idx / 294, rem = idx % 294, r = rem / 98, xx = rem % 98;
            int gy = y - 1 + r, gx = xx - 1, ci = cb*8 + c;
            float v = 0.f;
            if (gy >= 0 && gy < 96 && gx >= 0 && gx < 96)
                v = x[((n*64 + ci)*96 + gy)*96 + gx];
            in_sh[c][r][xx] = v;
        }
        for (int idx = tid; idx < 8*72*9; idx += 288) {
            int c = idx / 648, rem = idx % 648, tap = rem / 72, co_l = rem % 72;
            int co = coBase + co_l, ci = cb*8 + c;
            float w;
            if (co < 16)      w = wm[( co      *64 + ci)*9 + tap];
            else if (co < 80) w = wa[((co-16)*64 + ci)*9 + tap];
            else              w = wf[((co-80)*64 + ci)*9 + tap];
            w_sh[c][tap][co_l] = w;
        }
        __syncthreads();
#pragma unroll
        for (int c = 0; c < 8; ++c) {
            ull d[9];
            d[0] = pk2(in_sh[c][0][xcol],   in_sh[c][0][xcol]);
            d[1] = pk2(in_sh[c][0][xcol+1], in_sh[c][0][xcol+1]);
            d[2] = pk2(in_sh[c][0][xcol+2], in_sh[c][0][xcol+2]);
            d[3] = pk2(in_sh[c][1][xcol],   in_sh[c][1][xcol]);
            d[4] = pk2(in_sh[c][1][xcol+1], in_sh[c][1][xcol+1]);
            d[5] = pk2(in_sh[c][1][xcol+2], in_sh[c][1][xcol+2]);
            d[6] = pk2(in_sh[c][2][xcol],   in_sh[c][2][xcol]);
            d[7] = pk2(in_sh[c][2][xcol+1], in_sh[c][2][xcol+1]);
            d[8] = pk2(in_sh[c][2][xcol+2], in_sh[c][2][xcol+2]);
#pragma unroll
            for (int tap = 0; tap < 9; ++tap) {
                const ulonglong2* wp = (const ulonglong2*)&w_sh[c][tap][lane*24];
#pragma unroll
                for (int v = 0; v < 6; ++v) {
                    ulonglong2 w4 = wp[v];
                    acc2[2*v]   = fma2(d[tap], w4.x, acc2[2*v]);
                    acc2[2*v+1] = fma2(d[tap], w4.y, acc2[2*v+1]);
                }
            }
        }
    }

    const int tok = n*LL + y*96 + xcol;
    float acc[24];
#pragma unroll
    for (int m = 0; m < 12; ++m) upk2(acc2[m], acc[2*m], acc[2*m+1]);
#pragma unroll
    for (int m = 0; m < 24; ++m) {
        int co = coBase + lane*24 + m;
        if (co < 16) {
            g_xe[tok*16 + co] = fmaxf(acc[m] + bm[co], 0.f);
        } else if (co < 80) {
            g_ye[(size_t)tok*64 + (co-16)] = fmaxf(acc[m] + ba[co-16], 0.f);
        } else {
            g_fe[(size_t)tok*64 + (co-80)] = fmaxf(acc[m] + bf[co-80], 0.f);
        }
    }
}

// =======================================================================
// K2: LSH codes + normalized xm
// =======================================================================
__global__ __launch_bounds__(256) void code_kernel(const float* __restrict__ rot)
{
    __shared__ __align__(16) float rotT[4096];
    const int tid = threadIdx.x;
    for (int idx = tid; idx < 4096; idx += 256) {
        int hi = idx >> 4, f = idx & 15;
        rotT[idx] = rot[f*256 + hi];
    }
    __syncthreads();

    const int tg = blockIdx.x*256 + tid;
    const int n = tg / LL, t = tg % LL;

    const ulonglong2* ep = (const ulonglong2*)&g_xe[tg*16];
    ull ev[8];
#pragma unroll
    for (int i = 0; i < 4; ++i) { ulonglong2 v = ep[i]; ev[2*i] = v.x; ev[2*i+1] = v.y; }

    ull ssp = 0ull;
#pragma unroll
    for (int i = 0; i < 8; ++i) ssp = fma2(ev[i], ev[i], ssp);
    float slo, shi; upk2(ssp, slo, shi);
    float inv = 1.f / fmaxf(sqrtf(slo + shi), 5e-5f);
    ull invd = pk2(inv, inv);
    ulonglong2* xmp = (ulonglong2*)&g_xm[tg*16];
#pragma unroll
    for (int i = 0; i < 4; ++i) {
        ulonglong2 o;
        o.x = mul2_(ev[2*i], invd); o.y = mul2_(ev[2*i+1], invd);
        xmp[i] = o;
    }

#pragma unroll
    for (int h = 0; h < 4; ++h) {
        float best = -1e30f; int bi = 0;
        for (int i = 0; i < 64; ++i) {
            const ull* rr = (const ull*)&rotT[(h*64+i)*16];
            ull sp = 0ull;
#pragma unroll
            for (int j = 0; j < 8; ++j) sp = fma2(ev[j], rr[j], sp);
            float a, b; upk2(sp, a, b);
            float dd = a + b;
            if (dd > best) { best = dd; bi = i; }
        }
        g_code[(n*4+h)*LL + t] = (unsigned char)bi;
    }
}

// =======================================================================
// K3: per-(n,h) stable counting sort over 64 buckets -> g_perm
// =======================================================================
__global__ __launch_bounds__(256) void sort_kernel()
{
    const int seg = blockIdx.x;
    __shared__ int hist[64];
    __shared__ int running[64];
    __shared__ int wh[8][64];
    const int tid = threadIdx.x;
    const int w = tid >> 5, ln = tid & 31;

    if (tid < 64) hist[tid] = 0;
    __syncthreads();
    const unsigned char* code = &g_code[seg*LL];
    for (int t = tid; t < LL; t += 256) atomicAdd(&hist[code[t]], 1);
    __syncthreads();
    if (tid == 0) {
        int acc = 0;
        for (int b = 0; b < 64; ++b) { running[b] = acc; acc += hist[b]; }
    }
    __syncthreads();

    for (int tile = 0; tile < 36; ++tile) {
        int t = tile*256 + tid;
        int c = code[t];
        unsigned mask = __match_any_sync(0xffffffffu, c);
        int lanerank = __popc(mask & ((1u << ln) - 1u));
        ((int*)wh)[tid] = 0; ((int*)wh)[tid + 256] = 0;
        __syncthreads();
        if (lanerank == 0) wh[w][c] = __popc(mask);
        __syncthreads();
        int r = lanerank;
        for (int w2 = 0; w2 < w; ++w2) r += wh[w2][c];
        int pos = running[c] + r;
        __syncthreads();
        if (tid < 64) {
            int s = 0;
            for (int w2 = 0; w2 < 8; ++w2) s += wh[w2][tid];
            running[tid] += s;
        }
        __syncthreads();
        g_perm[seg*LL + pos] = t;
    }
}

// =======================================================================
// K4: H = relu(fe @ fc1_w^T + fc1_b)   (R12 version, known good)
// =======================================================================
__global__ __launch_bounds__(256) void hid_kernel(
    const float* __restrict__ fc1_w, const float* __restrict__ fc1_b)
{
    __shared__ __align__(16) float w_sh[144][68];
    __shared__ __align__(16) float fe_sh[32][68];
    __shared__ float b_sh[144];

    const int tid = threadIdx.x;
    for (int idx = tid; idx < 144*16; idx += 256) {
        int col = idx >> 4, kq = idx & 15;
        *(float4*)&w_sh[col][kq*4] = *(const float4*)&fc1_w[col*64 + kq*4];
    }
    if (tid < 144) b_sh[tid] = fc1_b[tid];
    const int tok0 = blockIdx.x * 32;
    for (int idx = tid; idx < 32*16; idx += 256) {
        int t = idx >> 4, kq = idx & 15;
        *(float4*)&fe_sh[t][kq*4] = *(const float4*)&g_fe[(size_t)(tok0+t)*64 + kq*4];
    }
    __syncthreads();

    const int cg = tid & 15;
    const int tg = tid >> 4;
    const int c0 = cg * 9;
    const int t0 = tg * 2;

    ull acc[18];
#pragma unroll
    for (int j = 0; j < 18; ++j) acc[j] = 0ull;

#pragma unroll
    for (int kk = 0; kk < 16; ++kk) {
        ulonglong2 f0 = *(const ulonglong2*)&fe_sh[t0][kk*4];
        ulonglong2 f1 = *(const ulonglong2*)&fe_sh[t0+1][kk*4];
#pragma unroll
        for (int j = 0; j < 9; ++j) {
            ulonglong2 w4 = *(const ulonglong2*)&w_sh[c0+j][kk*4];
            acc[j]   = fma2(f0.x, w4.x, acc[j]);
            acc[j]   = fma2(f0.y, w4.y, acc[j]);
            acc[9+j] = fma2(f1.x, w4.x, acc[9+j]);
            acc[9+j] = fma2(f1.y, w4.y, acc[9+j]);
        }
    }
#pragma unroll
    for (int t = 0; t < 2; ++t)
#pragma unroll
        for (int j = 0; j < 9; ++j) {
            float lo, hi; upk2(acc[t*9+j], lo, hi);
            float s = lo + hi + b_sh[c0+j];
            g_H[(size_t)(tok0 + t0 + t)*144 + c0 + j] = fmaxf(s, 0.f);
        }
}

// =======================================================================
// K4c: F[tok][i] = LOG2E*(fc2_b[i] + sum_e fc2_w[i][e]*H[tok][e])
// (R12 version, known good)
// =======================================================================
#define FB_HS 148
#define FB_WS 150
__global__ __launch_bounds__(512, 1) void fbig_kernel(
    const float* __restrict__ fc2_w, const float* __restrict__ fc2_b)
{
    extern __shared__ float fsm[];
    float* Hs = fsm;                    // [128][FB_HS]
    float* Ws = Hs + 128*FB_HS;         // [144][FB_WS]
    float* bs = Ws + 144*FB_WS;         // [144]

    const int tid  = threadIdx.x;
    const int tok0 = blockIdx.x * 128;

    for (int idx = tid; idx < 128*36; idx += 512) {
        int t = idx / 36, kq = idx % 36;
        *(float4*)&Hs[t*FB_HS + kq*4] =
            *(const float4*)&g_H[(size_t)(tok0+t)*144 + kq*4];
    }
    for (int idx = tid; idx < 144*72; idx += 512) {
        int c = idx / 72, kp = idx % 72;
        *(float2*)&Ws[c*FB_WS + kp*2] = *(const float2*)&fc2_w[c*144 + kp*2];
    }
    if (tid < 144) bs[tid] = fc2_b[tid];
    __syncthreads();

    const int tg = tid >> 4;
    const int cg = tid & 15;
    const int t0 = tg * 4;
    const int c0 = cg * 9;

    ull acc[36];
#pragma unroll
    for (int a = 0; a < 36; ++a) acc[a] = 0ull;

#pragma unroll 4
    for (int kp = 0; kp < 72; ++kp) {
        const int kk = kp*2;
        ull hv[4];
#pragma unroll
        for (int j = 0; j < 4; ++j) hv[j] = *(const ull*)&Hs[(t0+j)*FB_HS + kk];
#pragma unroll
        for (int c = 0; c < 9; ++c) {
            ull wv = *(const ull*)&Ws[(c0+c)*FB_WS + kk];
#pragma unroll
            for (int j = 0; j < 4; ++j)
                acc[j*9+c] = fma2(hv[j], wv, acc[j*9+c]);
        }
    }

#pragma unroll
    for (int j = 0; j < 4; ++j)
#pragma unroll
        for (int c = 0; c < 9; ++c) {
            float lo, hi; upk2(acc[j*9+c], lo, hi);
            g_F[(size_t)(tok0 + t0 + j)*144 + c0 + c] =
                LOG2E*(lo + hi + bs[c0+c]);
        }
}

// =======================================================================
// K5: attention v5 — direct gather (no prep). Per (n,h,chunk), 576 thr,
// 2 blocks/SM. Perms for all 3 neighbor chunks staged once per block.
// xe_sh pre-scaled by LOG2E (replaces xm-side scaling).
// =======================================================================
#define S_STR  148
#define KX_STR 18

__global__ __launch_bounds__(576, 2) void attn_kernel()
{
    extern __shared__ __align__(16) char smraw[];
    ull*   P2    = (ull*)smraw;                    // [48][144] dup pairs
    float* S     = (float*)(P2 + 48*144);          // [48][S_STR]
    float* Yt    = S  + 48*S_STR;                  // [48][64]
    float* Kxm   = Yt + 48*64;                     // [48][KX_STR]
    float* xe_sh = Kxm + 48*KX_STR;                // [144][16]
    float* Mt    = xe_sh + 144*16;                 // [4][144]
    float* alS   = Mt + 4*144;                     // [144]
    int*   pm_sh = (int*)(alS + 144);              // [3][144]: own, left, right

    const int cblk = blockIdx.x;
    const int h    = blockIdx.y;
    const int n    = blockIdx.z;
    const int seg  = n*4 + h;
    const int tid  = threadIdx.x;
    const int nbase = n*LL;

    // stage perms for chunks {cblk, cblk-1, cblk+1}
    if (tid < 432) {
        int dci = tid / 144, jr = tid % 144;
        int cc = (cblk + (dci == 1 ? 63 : (dci == 2 ? 1 : 0))) & 63;
        pm_sh[tid] = g_perm[seg*LL + cc*CHK + jr];
    }
    __syncthreads();
    for (int idx = tid; idx < 144*4; idx += 576) {
        int i = idx >> 2, c4 = idx & 3;
        int tokg = nbase + pm_sh[i];
        float4 v = *(const float4*)&g_xe[tokg*16 + c4*4];
        v.x *= LOG2E; v.y *= LOG2E; v.z *= LOG2E; v.w *= LOG2E;
        *(float4*)&xe_sh[i*16 + c4*4] = v;
    }

    const int kg = tid % 12;        // phase-A key group (4 keys)
    const int qg = tid / 12;        // phase-A query group (3 queries)
    const int q1 = tid % 144;       // phase-B1 query
    const int kg1 = tid / 144;      // phase-B1 key quarter (12 keys)
    const int qg2 = tid >> 4;       // phase-B2 query group (4 queries)
    const int eg2 = tid & 15;       // phase-B2 e group (4 floats)
    const int q0B = qg2 * 4;

    float m = -1e30f, l = 0.f;
    ull racc[8];
#pragma unroll
    for (int r = 0; r < 8; ++r) racc[r] = 0ull;

    for (int t = 0; t < 9; ++t) {
        const int dc = t / 3;                 // 0 own, 1 left, 2 right
        const int jr0 = (t % 3) * 48;
        const int pmb = dc*144 + jr0;

        __syncthreads();
        // gather tile directly from g_xm / g_F / g_ye via perm
        for (int idx = tid; idx < 48*56; idx += 576) {
            int r = idx / 56, c = idx % 56;
            int tokg = nbase + pm_sh[pmb + r];
            if (c < 4) {
                float4 v = *(const float4*)&g_xm[tokg*16 + c*4];
                float* d = &Kxm[r*KX_STR + c*4];
                *(float2*)d     = make_float2(v.x, v.y);
                *(float2*)(d+2) = make_float2(v.z, v.w);
            } else if (c < 40) {
                *(float4*)&S[r*S_STR + (c-4)*4] =
                    *(const float4*)&g_F[(size_t)tokg*144 + (c-4)*4];
            } else {
                *(float4*)&Yt[r*64 + (c-40)*4] =
                    *(const float4*)&g_ye[(size_t)tokg*64 + (c-40)*4];
            }
        }
        __syncthreads();

        // ---- phase A: 16-d dots, add into prefetched F logits ----
        {
            ull acc[12];
#pragma unroll
            for (int a = 0; a < 12; ++a) acc[a] = 0ull;
#pragma unroll
            for (int dd = 0; dd < 16; dd += 2) {
                ull qa = *(const ull*)&xe_sh[(3*qg+0)*16 + dd];
                ull qb = *(const ull*)&xe_sh[(3*qg+1)*16 + dd];
                ull qc = *(const ull*)&xe_sh[(3*qg+2)*16 + dd];
#pragma unroll
                for (int i = 0; i < 4; ++i) {
                    ull kv = *(const ull*)&Kxm[(kg + 12*i)*KX_STR + dd];
                    acc[0*4+i] = fma2(qa, kv, acc[0*4+i]);
                    acc[1*4+i] = fma2(qb, kv, acc[1*4+i]);
                    acc[2*4+i] = fma2(qc, kv, acc[2*4+i]);
                }
            }
#pragma unroll
            for (int j = 0; j < 3; ++j)
#pragma unroll
                for (int i = 0; i < 4; ++i) {
                    float lo, hi; upk2(acc[j*4+i], lo, hi);
                    S[(kg + 12*i)*S_STR + 3*qg + j] += lo + hi;
                }
        }
        __syncthreads();

        // ---- phase B1: tile max + P materialization + l quarters ----
        {
            float tm = -1e30f;
#pragma unroll
            for (int j = 0; j < 12; ++j)
                tm = fmaxf(tm, S[(kg1*12 + j)*S_STR + q1]);
            Mt[kg1*144 + q1] = tm;
        }
        __syncthreads();
        {
            float tmax = fmaxf(fmaxf(Mt[q1], Mt[144+q1]),
                               fmaxf(Mt[288+q1], Mt[432+q1]));
            float mn = fmaxf(m, tmax);
            float al = ex2f(m - mn);
            m = mn;
            l *= al;
            if (kg1 == 0) alS[q1] = al;
#pragma unroll
            for (int j = 0; j < 12; ++j) {
                int k = kg1*12 + j;
                float p = ex2f(S[k*S_STR + q1] - mn);
                l += p;
                P2[k*144 + q1] = pk2(p, p);
            }
        }
        __syncthreads();

        // ---- phase B2: register-tiled P.Y GEMM (4q x 4e per thread) ----
        {
            float a0 = alS[q0B], a1 = alS[q0B+1], a2 = alS[q0B+2], a3 = alS[q0B+3];
            racc[0] = mul2_(racc[0], pk2(a0,a0)); racc[1] = mul2_(racc[1], pk2(a0,a0));
            racc[2] = mul2_(racc[2], pk2(a1,a1)); racc[3] = mul2_(racc[3], pk2(a1,a1));
            racc[4] = mul2_(racc[4], pk2(a2,a2)); racc[5] = mul2_(racc[5], pk2(a2,a2));
            racc[6] = mul2_(racc[6], pk2(a3,a3)); racc[7] = mul2_(racc[7], pk2(a3,a3));
#pragma unroll 4
            for (int k = 0; k < 48; ++k) {
                ull p0 = P2[k*144 + q0B];
                ull p1 = P2[k*144 + q0B+1];
                ull pq2 = P2[k*144 + q0B+2];
                ull p3 = P2[k*144 + q0B+3];
                ulonglong2 yv = *(const ulonglong2*)&Yt[k*64 + eg2*4];
                racc[0] = fma2(p0,  yv.x, racc[0]); racc[1] = fma2(p0,  yv.y, racc[1]);
                racc[2] = fma2(p1,  yv.x, racc[2]); racc[3] = fma2(p1,  yv.y, racc[3]);
                racc[4] = fma2(pq2, yv.x, racc[4]); racc[5] = fma2(pq2, yv.y, racc[5]);
                racc[6] = fma2(p3,  yv.x, racc[6]); racc[7] = fma2(p3,  yv.y, racc[7]);
            }
        }
    }

    // ---- epilogue ----
    __syncthreads();
    Mt[kg1*144 + q1] = l;          // per-quarter l
    __syncthreads();
    if (tid < 144) {
        float lt = Mt[tid] + Mt[144+tid] + Mt[288+tid] + Mt[432+tid];
        alS[tid] = 1.f / lt;       // reuse alS as inv-l
        g_bsc[seg*LL + pm_sh[tid]] = (m + lg2f(lt)) * LN2;
    }
    __syncthreads();
    {
        float i0 = alS[q0B], i1 = alS[q0B+1], i2 = alS[q0B+2], i3 = alS[q0B+3];
        ull iv0 = pk2(i0,i0), iv1 = pk2(i1,i1), iv2 = pk2(i2,i2), iv3 = pk2(i3,i3);
        const int ebase = eg2*4;
#pragma unroll
        for (int j = 0; j < 4; ++j) {
            ull ivj = (j==0) ? iv0 : (j==1) ? iv1 : (j==2) ? iv2 : iv3;
            int tq = pm_sh[q0B + j];
            ulonglong2 o;
            o.x = mul2_(racc[2*j],   ivj);
            o.y = mul2_(racc[2*j+1], ivj);
            *(ulonglong2*)&g_ret[((size_t)seg*LL + tq)*64 + ebase] = o;
        }
    }
}

// =======================================================================
// K6: per-token softmax over heads + residual, NCHW output
// =======================================================================
__global__ __launch_bounds__(256) void final_kernel(
    const float* __restrict__ x, float* __restrict__ out)
{
    const int tg = blockIdx.x*256 + threadIdx.x;
    const int n = tg / LL, tt = tg % LL;
    float b[4];
    float mx = -1e30f;
#pragma unroll
    for (int h = 0; h < 4; ++h) {
        b[h] = g_bsc[(n*4+h)*LL + tt];
        mx = fmaxf(mx, b[h]);
    }
    float wsum = 0.f;
#pragma unroll
    for (int h = 0; h < 4; ++h) { b[h] = __expf(b[h] - mx); wsum += b[h]; }
    const float inv = 1.f / wsum;
#pragma unroll
    for (int c4 = 0; c4 < 16; ++c4) {
        float4 acc = {0.f, 0.f, 0.f, 0.f};
#pragma unroll
        for (int h = 0; h < 4; ++h) {
            float4 r = *(const float4*)&g_ret[((size_t)(n*4+h)*LL + tt)*64 + c4*4];
            float wv = b[h]*inv;
            acc.x += wv*r.x; acc.y += wv*r.y; acc.z += wv*r.z; acc.w += wv*r.w;
        }
        int c = c4*4;
        out[(n*64+c  )*LL + tt] = acc.x + x[(n*64+c  )*LL + tt];
        out[(n*64+c+1)*LL + tt] = acc.y + x[(n*64+c+1)*LL + tt];
        out[(n*64+c+2)*LL + tt] = acc.z + x[(n*64+c+2)*LL + tt];
        out[(n*64+c+3)*LL + tt] = acc.w + x[(n*64+c+3)*LL + tt];
    }
}

// =======================================================================
extern "C" void kernel_launch(void* const* d_in, const int* in_sizes, int n_in,
                              void* d_out, int out_size)
{
    const float* x     = (const float*)d_in[0];
    const float* rot   = (const float*)d_in[1];
    const float* wm    = (const float*)d_in[2];
    const float* bm    = (const float*)d_in[3];
    const float* wa    = (const float*)d_in[4];
    const float* ba    = (const float*)d_in[5];
    const float* wf    = (const float*)d_in[6];
    const float* bf    = (const float*)d_in[7];
    const float* fc1_w = (const float*)d_in[8];
    const float* fc1_b = (const float*)d_in[9];
    const float* fc2_w = (const float*)d_in[10];
    const float* fc2_b = (const float*)d_in[11];
    float* out = (float*)d_out;

    const int attn_smem = 48*144*8
        + (48*S_STR + 48*64 + 48*KX_STR + 144*16 + 4*144 + 144) * 4
        + 432*4;
    const int fbig_smem = (128*FB_HS + 144*FB_WS + 144) * 4;
    cudaFuncSetAttribute(attn_kernel,
                         cudaFuncAttributeMaxDynamicSharedMemorySize, attn_smem);
    cudaFuncSetAttribute(fbig_kernel,
                         cudaFuncAttributeMaxDynamicSharedMemorySize, fbig_smem);

    conv_kernel <<<dim3(96, 2, 2), dim3(96, 3)>>>(x, wm, bm, wa, ba, wf, bf);
    code_kernel <<<72, 256>>>(rot);
    sort_kernel <<<8, 256>>>();
    hid_kernel  <<<576, 256>>>(fc1_w, fc1_b);
    fbig_kernel <<<144, 512, fbig_smem>>>(fc2_w, fc2_b);
    attn_kernel <<<dim3(64, 4, 2), 576, attn_smem>>>();
    final_kernel<<<72, 256>>>(x, out);
}

// round 16
// speedup vs baseline: 1.1487x; 1.0364x over previous
#include <cuda_runtime.h>
#include <math.h>

#define NB 2
#define LL 9216
#define NHH 4
#define CHK 144
#define NCHK 64
#define TOKS (NB*LL)

// ---------------- static scratch ----------------
__device__ float g_xe[TOKS*16];
__device__ float g_xm[TOKS*16];
__device__ float g_ye[(size_t)TOKS*64];
__device__ float g_fe[(size_t)TOKS*64];
__device__ float g_H [(size_t)TOKS*144];
__device__ float g_F [(size_t)TOKS*144];
__device__ unsigned char g_code[NB*NHH*LL];
__device__ int   g_perm[NB*NHH*LL];
__device__ float g_bsc[NB*NHH*LL];
__device__ float g_ret[(size_t)NB*NHH*LL*64];

// ---------------- packed f32x2 helpers ----------------
typedef unsigned long long ull;
__device__ __forceinline__ ull pk2(float a, float b) {
    ull r; asm("mov.b64 %0,{%1,%2};" : "=l"(r) : "f"(a), "f"(b)); return r;
}
__device__ __forceinline__ void upk2(ull v, float& a, float& b) {
    asm("mov.b64 {%0,%1},%2;" : "=f"(a), "=f"(b) : "l"(v));
}
__device__ __forceinline__ ull fma2(ull a, ull b, ull c) {
    ull d; asm("fma.rn.f32x2 %0,%1,%2,%3;" : "=l"(d) : "l"(a), "l"(b), "l"(c)); return d;
}
__device__ __forceinline__ ull mul2_(ull a, ull b) {
    ull d; asm("mul.rn.f32x2 %0,%1,%2;" : "=l"(d) : "l"(a), "l"(b)); return d;
}
__device__ __forceinline__ float ex2f(float x) {
    float y; asm("ex2.approx.ftz.f32 %0,%1;" : "=f"(y) : "f"(x)); return y;
}
__device__ __forceinline__ float lg2f(float x) {
    float y; asm("lg2.approx.ftz.f32 %0,%1;" : "=f"(y) : "f"(x)); return y;
}
#define LOG2E 1.4426950408889634f
#define LN2   0.6931471805599453f

// =======================================================================
// K1: fused 3x3 SAME conv (144 out ch) + ReLU + (half0) LSH codes + xm
// grid (96=y, 2=n, 2=half), block (96, 3)
// =======================================================================
__global__ __launch_bounds__(288) void conv_kernel(
    const float* __restrict__ x,   const float* __restrict__ rot,
    const float* __restrict__ wm, const float* __restrict__ bm,
    const float* __restrict__ wa, const float* __restrict__ ba,
    const float* __restrict__ wf, const float* __restrict__ bf)
{
    __shared__ float in_sh[8][3][100];
    __shared__ __align__(16) float w_sh[8][9][72];   // reused as rotT after loop

    const int y    = blockIdx.x;
    const int n    = blockIdx.y;
    const int half = blockIdx.z;
    const int xcol = threadIdx.x;
    const int lane = threadIdx.y;
    const int tid  = xcol + 96*lane;
    const int coBase = half*72;

    ull acc2[12];
#pragma unroll
    for (int m = 0; m < 12; ++m) acc2[m] = 0ull;

    for (int cb = 0; cb < 8; ++cb) {
        __syncthreads();
        for (int idx = tid; idx < 8*3*98; idx += 288) {
            int c = idx / 294, rem = idx % 294, r = rem / 98, xx = rem % 98;
            int gy = y - 1 + r, gx = xx - 1, ci = cb*8 + c;
            float v = 0.f;
            if (gy >= 0 && gy < 96 && gx >= 0 && gx < 96)
                v = x[((n*64 + ci)*96 + gy)*96 + gx];
            in_sh[c][r][xx] = v;
        }
        for (int idx = tid; idx < 8*72*9; idx += 288) {
            int c = idx / 648, rem = idx % 648, tap = rem / 72, co_l = rem % 72;
            int co = coBase + co_l, ci = cb*8 + c;
            float w;
            if (co < 16)      w = wm[( co      *64 + ci)*9 + tap];
            else if (co < 80) w = wa[((co-16)*64 + ci)*9 + tap];
            else              w = wf[((co-80)*64 + ci)*9 + tap];
            w_sh[c][tap][co_l] = w;
        }
        __syncthreads();
#pragma unroll
        for (int c = 0; c < 8; ++c) {
            ull d[9];
            d[0] = pk2(in_sh[c][0][xcol],   in_sh[c][0][xcol]);
            d[1] = pk2(in_sh[c][0][xcol+1], in_sh[c][0][xcol+1]);
            d[2] = pk2(in_sh[c][0][xcol+2], in_sh[c][0][xcol+2]);
            d[3] = pk2(in_sh[c][1][xcol],   in_sh[c][1][xcol]);
            d[4] = pk2(in_sh[c][1][xcol+1], in_sh[c][1][xcol+1]);
            d[5] = pk2(in_sh[c][1][xcol+2], in_sh[c][1][xcol+2]);
            d[6] = pk2(in_sh[c][2][xcol],   in_sh[c][2][xcol]);
            d[7] = pk2(in_sh[c][2][xcol+1], in_sh[c][2][xcol+1]);
            d[8] = pk2(in_sh[c][2][xcol+2], in_sh[c][2][xcol+2]);
#pragma unroll
            for (int tap = 0; tap < 9; ++tap) {
                const ulonglong2* wp = (const ulonglong2*)&w_sh[c][tap][lane*24];
#pragma unroll
                for (int v = 0; v < 6; ++v) {
                    ulonglong2 w4 = wp[v];
                    acc2[2*v]   = fma2(d[tap], w4.x, acc2[2*v]);
                    acc2[2*v+1] = fma2(d[tap], w4.y, acc2[2*v+1]);
                }
            }
        }
    }

    const int tok = n*LL + y*96 + xcol;
    float acc[24];
#pragma unroll
    for (int m = 0; m < 12; ++m) upk2(acc2[m], acc[2*m], acc[2*m+1]);
#pragma unroll
    for (int m = 0; m < 24; ++m) {
        int co = coBase + lane*24 + m;
        if (co < 16) {
            g_xe[tok*16 + co] = fmaxf(acc[m] + bm[co], 0.f);
        } else if (co < 80) {
            g_ye[(size_t)tok*64 + (co-16)] = fmaxf(acc[m] + ba[co-16], 0.f);
        } else {
            g_fe[(size_t)tok*64 + (co-80)] = fmaxf(acc[m] + bf[co-80], 0.f);
        }
    }

    // ---- fused LSH codes + normalized xm (half-0 blocks; lane-0 has xe) ----
    if (half == 1) return;
    __syncthreads();   // conv compute done; w_sh free
    float* rotT = &w_sh[0][0][0];   // 4096 floats
    for (int idx = tid; idx < 4096; idx += 288) {
        int hi = idx >> 4, f = idx & 15;
        rotT[idx] = rot[f*256 + hi];     // rot (16, 4, 64) -> [(h*64+i)*16+f]
    }
    __syncthreads();
    if (lane != 0) return;

    ull ev[8];
#pragma unroll
    for (int m2 = 0; m2 < 8; ++m2) {
        float a = fmaxf(acc[2*m2]   + bm[2*m2],   0.f);
        float b = fmaxf(acc[2*m2+1] + bm[2*m2+1], 0.f);
        ev[m2] = pk2(a, b);
    }
    ull ssp = 0ull;
#pragma unroll
    for (int i = 0; i < 8; ++i) ssp = fma2(ev[i], ev[i], ssp);
    float slo, shi; upk2(ssp, slo, shi);
    float inv = 1.f / fmaxf(sqrtf(slo + shi), 5e-5f);
    ull invd = pk2(inv, inv);
    ulonglong2* xmp = (ulonglong2*)&g_xm[tok*16];
#pragma unroll
    for (int i = 0; i < 4; ++i) {
        ulonglong2 o;
        o.x = mul2_(ev[2*i], invd); o.y = mul2_(ev[2*i+1], invd);
        xmp[i] = o;
    }
    const int t = y*96 + xcol;
#pragma unroll
    for (int h = 0; h < 4; ++h) {
        float best = -1e30f; int bi = 0;
        for (int i = 0; i < 64; ++i) {
            const ull* rr = (const ull*)&rotT[(h*64+i)*16];
            ull sp = 0ull;
#pragma unroll
            for (int j = 0; j < 8; ++j) sp = fma2(ev[j], rr[j], sp);
            float a, b; upk2(sp, a, b);
            float dd = a + b;
            if (dd > best) { best = dd; bi = i; }
        }
        g_code[(n*4+h)*LL + t] = (unsigned char)bi;
    }
}

// =======================================================================
// K2: fused dispatch — blocks 0..7: counting sort; blocks 8..583: hid GEMM
// =======================================================================
__global__ __launch_bounds__(256) void sorthid_kernel(
    const float* __restrict__ fc1_w, const float* __restrict__ fc1_b)
{
    __shared__ int hist[64];
    __shared__ int running[64];
    __shared__ int wh[8][64];
    __shared__ __align__(16) float w_sh[144][68];
    __shared__ __align__(16) float fe_sh[32][68];
    __shared__ float b_sh[144];

    const int tid = threadIdx.x;

    if (blockIdx.x < 8) {
        // -------- sort body --------
        const int seg = blockIdx.x;
        const int w = tid >> 5, ln = tid & 31;

        if (tid < 64) hist[tid] = 0;
        __syncthreads();
        const unsigned char* code = &g_code[seg*LL];
        for (int t = tid; t < LL; t += 256) atomicAdd(&hist[code[t]], 1);
        __syncthreads();
        if (tid == 0) {
            int acc = 0;
            for (int b = 0; b < 64; ++b) { running[b] = acc; acc += hist[b]; }
        }
        __syncthreads();

        for (int tile = 0; tile < 36; ++tile) {
            int t = tile*256 + tid;
            int c = code[t];
            unsigned mask = __match_any_sync(0xffffffffu, c);
            int lanerank = __popc(mask & ((1u << ln) - 1u));
            ((int*)wh)[tid] = 0; ((int*)wh)[tid + 256] = 0;
            __syncthreads();
            if (lanerank == 0) wh[w][c] = __popc(mask);
            __syncthreads();
            int r = lanerank;
            for (int w2 = 0; w2 < w; ++w2) r += wh[w2][c];
            int pos = running[c] + r;
            __syncthreads();
            if (tid < 64) {
                int s = 0;
                for (int w2 = 0; w2 < 8; ++w2) s += wh[w2][tid];
                running[tid] += s;
            }
            __syncthreads();
            g_perm[seg*LL + pos] = t;
        }
        return;
    }

    // -------- hid body: H = relu(fe @ fc1_w^T + fc1_b) --------
    const int blk = blockIdx.x - 8;
    for (int idx = tid; idx < 144*16; idx += 256) {
        int col = idx >> 4, kq = idx & 15;
        *(float4*)&w_sh[col][kq*4] = *(const float4*)&fc1_w[col*64 + kq*4];
    }
    if (tid < 144) b_sh[tid] = fc1_b[tid];
    const int tok0 = blk * 32;
    for (int idx = tid; idx < 32*16; idx += 256) {
        int t = idx >> 4, kq = idx & 15;
        *(float4*)&fe_sh[t][kq*4] = *(const float4*)&g_fe[(size_t)(tok0+t)*64 + kq*4];
    }
    __syncthreads();

    const int cg = tid & 15;
    const int tg = tid >> 4;
    const int c0 = cg * 9;
    const int t0 = tg * 2;

    ull acc[18];
#pragma unroll
    for (int j = 0; j < 18; ++j) acc[j] = 0ull;

#pragma unroll
    for (int kk = 0; kk < 16; ++kk) {
        ulonglong2 f0 = *(const ulonglong2*)&fe_sh[t0][kk*4];
        ulonglong2 f1 = *(const ulonglong2*)&fe_sh[t0+1][kk*4];
#pragma unroll
        for (int j = 0; j < 9; ++j) {
            ulonglong2 w4 = *(const ulonglong2*)&w_sh[c0+j][kk*4];
            acc[j]   = fma2(f0.x, w4.x, acc[j]);
            acc[j]   = fma2(f0.y, w4.y, acc[j]);
            acc[9+j] = fma2(f1.x, w4.x, acc[9+j]);
            acc[9+j] = fma2(f1.y, w4.y, acc[9+j]);
        }
    }
#pragma unroll
    for (int t = 0; t < 2; ++t)
#pragma unroll
        for (int j = 0; j < 9; ++j) {
            float lo, hi; upk2(acc[t*9+j], lo, hi);
            float s = lo + hi + b_sh[c0+j];
            g_H[(size_t)(tok0 + t0 + t)*144 + c0 + j] = fmaxf(s, 0.f);
        }
}

// =======================================================================
// K3: F[tok][i] = LOG2E*(fc2_b[i] + sum_e fc2_w[i][e]*H[tok][e])
// =======================================================================
#define FB_HS 148
#define FB_WS 150
__global__ __launch_bounds__(512, 1) void fbig_kernel(
    const float* __restrict__ fc2_w, const float* __restrict__ fc2_b)
{
    extern __shared__ float fsm[];
    float* Hs = fsm;                    // [128][FB_HS]
    float* Ws = Hs + 128*FB_HS;         // [144][FB_WS]
    float* bs = Ws + 144*FB_WS;         // [144]

    const int tid  = threadIdx.x;
    const int tok0 = blockIdx.x * 128;

    for (int idx = tid; idx < 128*36; idx += 512) {
        int t = idx / 36, kq = idx % 36;
        *(float4*)&Hs[t*FB_HS + kq*4] =
            *(const float4*)&g_H[(size_t)(tok0+t)*144 + kq*4];
    }
    for (int idx = tid; idx < 144*72; idx += 512) {
        int c = idx / 72, kp = idx % 72;
        *(float2*)&Ws[c*FB_WS + kp*2] = *(const float2*)&fc2_w[c*144 + kp*2];
    }
    if (tid < 144) bs[tid] = fc2_b[tid];
    __syncthreads();

    const int tg = tid >> 4;
    const int cg = tid & 15;
    const int t0 = tg * 4;
    const int c0 = cg * 9;

    ull acc[36];
#pragma unroll
    for (int a = 0; a < 36; ++a) acc[a] = 0ull;

#pragma unroll 4
    for (int kp = 0; kp < 72; ++kp) {
        const int kk = kp*2;
        ull hv[4];
#pragma unroll
        for (int j = 0; j < 4; ++j) hv[j] = *(const ull*)&Hs[(t0+j)*FB_HS + kk];
#pragma unroll
        for (int c = 0; c < 9; ++c) {
            ull wv = *(const ull*)&Ws[(c0+c)*FB_WS + kk];
#pragma unroll
            for (int j = 0; j < 4; ++j)
                acc[j*9+c] = fma2(hv[j], wv, acc[j*9+c]);
        }
    }

#pragma unroll
    for (int j = 0; j < 4; ++j)
#pragma unroll
        for (int c = 0; c < 9; ++c) {
            float lo, hi; upk2(acc[j*9+c], lo, hi);
            g_F[(size_t)(tok0 + t0 + j)*144 + c0 + c] =
                LOG2E*(lo + hi + bs[c0+c]);
        }
}

// =======================================================================
// K4: attention v5 (R15, unchanged) — direct gather, 576 thr, 2 blocks/SM
// =======================================================================
#define S_STR  148
#define KX_STR 18

__global__ __launch_bounds__(576, 2) void attn_kernel()
{
    extern __shared__ __align__(16) char smraw[];
    ull*   P2    = (ull*)smraw;                    // [48][144] dup pairs
    float* S     = (float*)(P2 + 48*144);          // [48][S_STR]
    float* Yt    = S  + 48*S_STR;                  // [48][64]
    float* Kxm   = Yt + 48*64;                     // [48][KX_STR]
    float* xe_sh = Kxm + 48*KX_STR;                // [144][16]
    float* Mt    = xe_sh + 144*16;                 // [4][144]
    float* alS   = Mt + 4*144;                     // [144]
    int*   pm_sh = (int*)(alS + 144);              // [3][144]: own, left, right

    const int cblk = blockIdx.x;
    const int h    = blockIdx.y;
    const int n    = blockIdx.z;
    const int seg  = n*4 + h;
    const int tid  = threadIdx.x;
    const int nbase = n*LL;

    if (tid < 432) {
        int dci = tid / 144, jr = tid % 144;
        int cc = (cblk + (dci == 1 ? 63 : (dci == 2 ? 1 : 0))) & 63;
        pm_sh[tid] = g_perm[seg*LL + cc*CHK + jr];
    }
    __syncthreads();
    for (int idx = tid; idx < 144*4; idx += 576) {
        int i = idx >> 2, c4 = idx & 3;
        int tokg = nbase + pm_sh[i];
        float4 v = *(const float4*)&g_xe[tokg*16 + c4*4];
        v.x *= LOG2E; v.y *= LOG2E; v.z *= LOG2E; v.w *= LOG2E;
        *(float4*)&xe_sh[i*16 + c4*4] = v;
    }

    const int kg = tid % 12;
    const int qg = tid / 12;
    const int q1 = tid % 144;
    const int kg1 = tid / 144;
    const int qg2 = tid >> 4;
    const int eg2 = tid & 15;
    const int q0B = qg2 * 4;

    float m = -1e30f, l = 0.f;
    ull racc[8];
#pragma unroll
    for (int r = 0; r < 8; ++r) racc[r] = 0ull;

    for (int t = 0; t < 9; ++t) {
        const int dc = t / 3;
        const int jr0 = (t % 3) * 48;
        const int pmb = dc*144 + jr0;

        __syncthreads();
        for (int idx = tid; idx < 48*56; idx += 576) {
            int r = idx / 56, c = idx % 56;
            int tokg = nbase + pm_sh[pmb + r];
            if (c < 4) {
                float4 v = *(const float4*)&g_xm[tokg*16 + c*4];
                float* d = &Kxm[r*KX_STR + c*4];
                *(float2*)d     = make_float2(v.x, v.y);
                *(float2*)(d+2) = make_float2(v.z, v.w);
            } else if (c < 40) {
                *(float4*)&S[r*S_STR + (c-4)*4] =
                    *(const float4*)&g_F[(size_t)tokg*144 + (c-4)*4];
            } else {
                *(float4*)&Yt[r*64 + (c-40)*4] =
                    *(const float4*)&g_ye[(size_t)tokg*64 + (c-40)*4];
            }
        }
        __syncthreads();

        // ---- phase A ----
        {
            ull acc[12];
#pragma unroll
            for (int a = 0; a < 12; ++a) acc[a] = 0ull;
#pragma unroll
            for (int dd = 0; dd < 16; dd += 2) {
                ull qa = *(const ull*)&xe_sh[(3*qg+0)*16 + dd];
                ull qb = *(const ull*)&xe_sh[(3*qg+1)*16 + dd];
                ull qc = *(const ull*)&xe_sh[(3*qg+2)*16 + dd];
#pragma unroll
                for (int i = 0; i < 4; ++i) {
                    ull kv = *(const ull*)&Kxm[(kg + 12*i)*KX_STR + dd];
                    acc[0*4+i] = fma2(qa, kv, acc[0*4+i]);
                    acc[1*4+i] = fma2(qb, kv, acc[1*4+i]);
                    acc[2*4+i] = fma2(qc, kv, acc[2*4+i]);
                }
            }
#pragma unroll
            for (int j = 0; j < 3; ++j)
#pragma unroll
                for (int i = 0; i < 4; ++i) {
                    float lo, hi; upk2(acc[j*4+i], lo, hi);
                    S[(kg + 12*i)*S_STR + 3*qg + j] += lo + hi;
                }
        }
        __syncthreads();

        // ---- phase B1 ----
        {
            float tm = -1e30f;
#pragma unroll
            for (int j = 0; j < 12; ++j)
                tm = fmaxf(tm, S[(kg1*12 + j)*S_STR + q1]);
            Mt[kg1*144 + q1] = tm;
        }
        __syncthreads();
        {
            float tmax = fmaxf(fmaxf(Mt[q1], Mt[144+q1]),
                               fmaxf(Mt[288+q1], Mt[432+q1]));
            float mn = fmaxf(m, tmax);
            float al = ex2f(m - mn);
            m = mn;
            l *= al;
            if (kg1 == 0) alS[q1] = al;
#pragma unroll
            for (int j = 0; j < 12; ++j) {
                int k = kg1*12 + j;
                float p = ex2f(S[k*S_STR + q1] - mn);
                l += p;
                P2[k*144 + q1] = pk2(p, p);
            }
        }
        __syncthreads();

        // ---- phase B2 ----
        {
            float a0 = alS[q0B], a1 = alS[q0B+1], a2 = alS[q0B+2], a3 = alS[q0B+3];
            racc[0] = mul2_(racc[0], pk2(a0,a0)); racc[1] = mul2_(racc[1], pk2(a0,a0));
            racc[2] = mul2_(racc[2], pk2(a1,a1)); racc[3] = mul2_(racc[3], pk2(a1,a1));
            racc[4] = mul2_(racc[4], pk2(a2,a2)); racc[5] = mul2_(racc[5], pk2(a2,a2));
            racc[6] = mul2_(racc[6], pk2(a3,a3)); racc[7] = mul2_(racc[7], pk2(a3,a3));
#pragma unroll 4
            for (int k = 0; k < 48; ++k) {
                ull p0 = P2[k*144 + q0B];
                ull p1 = P2[k*144 + q0B+1];
                ull pq2 = P2[k*144 + q0B+2];
                ull p3 = P2[k*144 + q0B+3];
                ulonglong2 yv = *(const ulonglong2*)&Yt[k*64 + eg2*4];
                racc[0] = fma2(p0,  yv.x, racc[0]); racc[1] = fma2(p0,  yv.y, racc[1]);
                racc[2] = fma2(p1,  yv.x, racc[2]); racc[3] = fma2(p1,  yv.y, racc[3]);
                racc[4] = fma2(pq2, yv.x, racc[4]); racc[5] = fma2(pq2, yv.y, racc[5]);
                racc[6] = fma2(p3,  yv.x, racc[6]); racc[7] = fma2(p3,  yv.y, racc[7]);
            }
        }
    }

    // ---- epilogue ----
    __syncthreads();
    Mt[kg1*144 + q1] = l;
    __syncthreads();
    if (tid < 144) {
        float lt = Mt[tid] + Mt[144+tid] + Mt[288+tid] + Mt[432+tid];
        alS[tid] = 1.f / lt;
        g_bsc[seg*LL + pm_sh[tid]] = (m + lg2f(lt)) * LN2;
    }
    __syncthreads();
    {
        float i0 = alS[q0B], i1 = alS[q0B+1], i2 = alS[q0B+2], i3 = alS[q0B+3];
        ull iv0 = pk2(i0,i0), iv1 = pk2(i1,i1), iv2 = pk2(i2,i2), iv3 = pk2(i3,i3);
        const int ebase = eg2*4;
#pragma unroll
        for (int j = 0; j < 4; ++j) {
            ull ivj = (j==0) ? iv0 : (j==1) ? iv1 : (j==2) ? iv2 : iv3;
            int tq = pm_sh[q0B + j];
            ulonglong2 o;
            o.x = mul2_(racc[2*j],   ivj);
            o.y = mul2_(racc[2*j+1], ivj);
            *(ulonglong2*)&g_ret[((size_t)seg*LL + tq)*64 + ebase] = o;
        }
    }
}

// =======================================================================
// K5: per-token softmax over heads + residual, NCHW output
// =======================================================================
__global__ __launch_bounds__(256) void final_kernel(
    const float* __restrict__ x, float* __restrict__ out)
{
    const int tg = blockIdx.x*256 + threadIdx.x;
    const int n = tg / LL, tt = tg % LL;
    float b[4];
    float mx = -1e30f;
#pragma unroll
    for (int h = 0; h < 4; ++h) {
        b[h] = g_bsc[(n*4+h)*LL + tt];
        mx = fmaxf(mx, b[h]);
    }
    float wsum = 0.f;
#pragma unroll
    for (int h = 0; h < 4; ++h) { b[h] = __expf(b[h] - mx); wsum += b[h]; }
    const float inv = 1.f / wsum;
#pragma unroll
    for (int c4 = 0; c4 < 16; ++c4) {
        float4 acc = {0.f, 0.f, 0.f, 0.f};
#pragma unroll
        for (int h = 0; h < 4; ++h) {
            float4 r = *(const float4*)&g_ret[((size_t)(n*4+h)*LL + tt)*64 + c4*4];
            float wv = b[h]*inv;
            acc.x += wv*r.x; acc.y += wv*r.y; acc.z += wv*r.z; acc.w += wv*r.w;
        }
        int c = c4*4;
        out[(n*64+c  )*LL + tt] = acc.x + x[(n*64+c  )*LL + tt];
        out[(n*64+c+1)*LL + tt] = acc.y + x[(n*64+c+1)*LL + tt];
        out[(n*64+c+2)*LL + tt] = acc.z + x[(n*64+c+2)*LL + tt];
        out[(n*64+c+3)*LL + tt] = acc.w + x[(n*64+c+3)*LL + tt];
    }
}

// =======================================================================
extern "C" void kernel_launch(void* const* d_in, const int* in_sizes, int n_in,
                              void* d_out, int out_size)
{
    const float* x     = (const float*)d_in[0];
    const float* rot   = (const float*)d_in[1];
    const float* wm    = (const float*)d_in[2];
    const float* bm    = (const float*)d_in[3];
    const float* wa    = (const float*)d_in[4];
    const float* ba    = (const float*)d_in[5];
    const float* wf    = (const float*)d_in[6];
    const float* bf    = (const float*)d_in[7];
    const float* fc1_w = (const float*)d_in[8];
    const float* fc1_b = (const float*)d_in[9];
    const float* fc2_w = (const float*)d_in[10];
    const float* fc2_b = (const float*)d_in[11];
    float* out = (float*)d_out;

    const int attn_smem = 48*144*8
        + (48*S_STR + 48*64 + 48*KX_STR + 144*16 + 4*144 + 144) * 4
        + 432*4;
    const int fbig_smem = (128*FB_HS + 144*FB_WS + 144) * 4;
    cudaFuncSetAttribute(attn_kernel,
                         cudaFuncAttributeMaxDynamicSharedMemorySize, attn_smem);
    cudaFuncSetAttribute(fbig_kernel,
                         cudaFuncAttributeMaxDynamicSharedMemorySize, fbig_smem);

    conv_kernel    <<<dim3(96, 2, 2), dim3(96, 3)>>>(x, rot, wm, bm, wa, ba, wf, bf);
    sorthid_kernel <<<584, 256>>>(fc1_w, fc1_b);
    fbig_kernel    <<<144, 512, fbig_smem>>>(fc2_w, fc2_b);
    attn_kernel    <<<dim3(64, 4, 2), 576, attn_smem>>>();
    final_kernel   <<<72, 256>>>(x, out);
}

// round 17
// speedup vs baseline: 1.2110x; 1.0542x over previous
#include <cuda_runtime.h>
#include <math.h>

#define NB 2
#define LL 9216
#define NHH 4
#define CHK 144
#define NCHK 64
#define TOKS (NB*LL)

// ---------------- static scratch ----------------
__device__ float g_xe[TOKS*16];
__device__ float g_xm[TOKS*16];
__device__ float g_ye[(size_t)TOKS*64];
__device__ float g_fe[(size_t)TOKS*64];
__device__ float g_H [(size_t)TOKS*144];
__device__ float g_F [(size_t)TOKS*144];
__device__ unsigned char g_code[NB*NHH*LL];
__device__ int   g_perm[NB*NHH*LL];
__device__ float g_bsc[NB*NHH*LL];
__device__ float g_ret[(size_t)NB*NHH*LL*64];

// ---------------- packed f32x2 helpers ----------------
typedef unsigned long long ull;
__device__ __forceinline__ ull pk2(float a, float b) {
    ull r; asm("mov.b64 %0,{%1,%2};" : "=l"(r) : "f"(a), "f"(b)); return r;
}
__device__ __forceinline__ void upk2(ull v, float& a, float& b) {
    asm("mov.b64 {%0,%1},%2;" : "=f"(a), "=f"(b) : "l"(v));
}
__device__ __forceinline__ ull fma2(ull a, ull b, ull c) {
    ull d; asm("fma.rn.f32x2 %0,%1,%2,%3;" : "=l"(d) : "l"(a), "l"(b), "l"(c)); return d;
}
__device__ __forceinline__ ull mul2_(ull a, ull b) {
    ull d; asm("mul.rn.f32x2 %0,%1,%2;" : "=l"(d) : "l"(a), "l"(b)); return d;
}
__device__ __forceinline__ float ex2f(float x) {
    float y; asm("ex2.approx.ftz.f32 %0,%1;" : "=f"(y) : "f"(x)); return y;
}
__device__ __forceinline__ float lg2f(float x) {
    float y; asm("lg2.approx.ftz.f32 %0,%1;" : "=f"(y) : "f"(x)); return y;
}
#define LOG2E 1.4426950408889634f
#define LN2   0.6931471805599453f

// =======================================================================
// K1: fused 3x3 SAME conv (144 out ch) + ReLU + (half0) LSH codes + xm
// =======================================================================
__global__ __launch_bounds__(288) void conv_kernel(
    const float* __restrict__ x,   const float* __restrict__ rot,
    const float* __restrict__ wm, const float* __restrict__ bm,
    const float* __restrict__ wa, const float* __restrict__ ba,
    const float* __restrict__ wf, const float* __restrict__ bf)
{
    __shared__ float in_sh[8][3][100];
    __shared__ __align__(16) float w_sh[8][9][72];   // reused as rotT after loop

    const int y    = blockIdx.x;
    const int n    = blockIdx.y;
    const int half = blockIdx.z;
    const int xcol = threadIdx.x;
    const int lane = threadIdx.y;
    const int tid  = xcol + 96*lane;
    const int coBase = half*72;

    ull acc2[12];
#pragma unroll
    for (int m = 0; m < 12; ++m) acc2[m] = 0ull;

    for (int cb = 0; cb < 8; ++cb) {
        __syncthreads();
        for (int idx = tid; idx < 8*3*98; idx += 288) {
            int c = idx / 294, rem = idx % 294, r = rem / 98, xx = rem % 98;
            int gy = y - 1 + r, gx = xx - 1, ci = cb*8 + c;
            float v = 0.f;
            if (gy >= 0 && gy < 96 && gx >= 0 && gx < 96)
                v = x[((n*64 + ci)*96 + gy)*96 + gx];
            in_sh[c][r][xx] = v;
        }
        for (int idx = tid; idx < 8*72*9; idx += 288) {
            int c = idx / 648, rem = idx % 648, tap = rem / 72, co_l = rem % 72;
            int co = coBase + co_l, ci = cb*8 + c;
            float w;
            if (co < 16)      w = wm[( co      *64 + ci)*9 + tap];
            else if (co < 80) w = wa[((co-16)*64 + ci)*9 + tap];
            else              w = wf[((co-80)*64 + ci)*9 + tap];
            w_sh[c][tap][co_l] = w;
        }
        __syncthreads();
#pragma unroll
        for (int c = 0; c < 8; ++c) {
            ull d[9];
            d[0] = pk2(in_sh[c][0][xcol],   in_sh[c][0][xcol]);
            d[1] = pk2(in_sh[c][0][xcol+1], in_sh[c][0][xcol+1]);
            d[2] = pk2(in_sh[c][0][xcol+2], in_sh[c][0][xcol+2]);
            d[3] = pk2(in_sh[c][1][xcol],   in_sh[c][1][xcol]);
            d[4] = pk2(in_sh[c][1][xcol+1], in_sh[c][1][xcol+1]);
            d[5] = pk2(in_sh[c][1][xcol+2], in_sh[c][1][xcol+2]);
            d[6] = pk2(in_sh[c][2][xcol],   in_sh[c][2][xcol]);
            d[7] = pk2(in_sh[c][2][xcol+1], in_sh[c][2][xcol+1]);
            d[8] = pk2(in_sh[c][2][xcol+2], in_sh[c][2][xcol+2]);
#pragma unroll
            for (int tap = 0; tap < 9; ++tap) {
                const ulonglong2* wp = (const ulonglong2*)&w_sh[c][tap][lane*24];
#pragma unroll
                for (int v = 0; v < 6; ++v) {
                    ulonglong2 w4 = wp[v];
                    acc2[2*v]   = fma2(d[tap], w4.x, acc2[2*v]);
                    acc2[2*v+1] = fma2(d[tap], w4.y, acc2[2*v+1]);
                }
            }
        }
    }

    const int tok = n*LL + y*96 + xcol;
    float acc[24];
#pragma unroll
    for (int m = 0; m < 12; ++m) upk2(acc2[m], acc[2*m], acc[2*m+1]);
#pragma unroll
    for (int m = 0; m < 24; ++m) {
        int co = coBase + lane*24 + m;
        if (co < 16) {
            g_xe[tok*16 + co] = fmaxf(acc[m] + bm[co], 0.f);
        } else if (co < 80) {
            g_ye[(size_t)tok*64 + (co-16)] = fmaxf(acc[m] + ba[co-16], 0.f);
        } else {
            g_fe[(size_t)tok*64 + (co-80)] = fmaxf(acc[m] + bf[co-80], 0.f);
        }
    }

    // ---- fused LSH codes + normalized xm (half-0 blocks; lane-0 has xe) ----
    if (half == 1) return;
    __syncthreads();
    float* rotT = &w_sh[0][0][0];   // 4096 floats
    for (int idx = tid; idx < 4096; idx += 288) {
        int hi = idx >> 4, f = idx & 15;
        rotT[idx] = rot[f*256 + hi];
    }
    __syncthreads();
    if (lane != 0) return;

    ull ev[8];
#pragma unroll
    for (int m2 = 0; m2 < 8; ++m2) {
        float a = fmaxf(acc[2*m2]   + bm[2*m2],   0.f);
        float b = fmaxf(acc[2*m2+1] + bm[2*m2+1], 0.f);
        ev[m2] = pk2(a, b);
    }
    ull ssp = 0ull;
#pragma unroll
    for (int i = 0; i < 8; ++i) ssp = fma2(ev[i], ev[i], ssp);
    float slo, shi; upk2(ssp, slo, shi);
    float inv = 1.f / fmaxf(sqrtf(slo + shi), 5e-5f);
    ull invd = pk2(inv, inv);
    ulonglong2* xmp = (ulonglong2*)&g_xm[tok*16];
#pragma unroll
    for (int i = 0; i < 4; ++i) {
        ulonglong2 o;
        o.x = mul2_(ev[2*i], invd); o.y = mul2_(ev[2*i+1], invd);
        xmp[i] = o;
    }
    const int t = y*96 + xcol;
#pragma unroll
    for (int h = 0; h < 4; ++h) {
        float best = -1e30f; int bi = 0;
        for (int i = 0; i < 64; ++i) {
            const ull* rr = (const ull*)&rotT[(h*64+i)*16];
            ull sp = 0ull;
#pragma unroll
            for (int j = 0; j < 8; ++j) sp = fma2(ev[j], rr[j], sp);
            float a, b; upk2(sp, a, b);
            float dd = a + b;
            if (dd > best) { best = dd; bi = i; }
        }
        g_code[(n*4+h)*LL + t] = (unsigned char)bi;
    }
}

// =======================================================================
// K2: fused dispatch — blocks 0..7: counting sort; blocks 8..583: hid GEMM
// =======================================================================
__global__ __launch_bounds__(256) void sorthid_kernel(
    const float* __restrict__ fc1_w, const float* __restrict__ fc1_b)
{
    __shared__ int hist[64];
    __shared__ int running[64];
    __shared__ int wh[8][64];
    __shared__ __align__(16) float w_sh[144][68];
    __shared__ __align__(16) float fe_sh[32][68];
    __shared__ float b_sh[144];

    const int tid = threadIdx.x;

    if (blockIdx.x < 8) {
        const int seg = blockIdx.x;
        const int w = tid >> 5, ln = tid & 31;

        if (tid < 64) hist[tid] = 0;
        __syncthreads();
        const unsigned char* code = &g_code[seg*LL];
        for (int t = tid; t < LL; t += 256) atomicAdd(&hist[code[t]], 1);
        __syncthreads();
        if (tid == 0) {
            int acc = 0;
            for (int b = 0; b < 64; ++b) { running[b] = acc; acc += hist[b]; }
        }
        __syncthreads();

        for (int tile = 0; tile < 36; ++tile) {
            int t = tile*256 + tid;
            int c = code[t];
            unsigned mask = __match_any_sync(0xffffffffu, c);
            int lanerank = __popc(mask & ((1u << ln) - 1u));
            ((int*)wh)[tid] = 0; ((int*)wh)[tid + 256] = 0;
            __syncthreads();
            if (lanerank == 0) wh[w][c] = __popc(mask);
            __syncthreads();
            int r = lanerank;
            for (int w2 = 0; w2 < w; ++w2) r += wh[w2][c];
            int pos = running[c] + r;
            __syncthreads();
            if (tid < 64) {
                int s = 0;
                for (int w2 = 0; w2 < 8; ++w2) s += wh[w2][tid];
                running[tid] += s;
            }
            __syncthreads();
            g_perm[seg*LL + pos] = t;
        }
        return;
    }

    const int blk = blockIdx.x - 8;
    for (int idx = tid; idx < 144*16; idx += 256) {
        int col = idx >> 4, kq = idx & 15;
        *(float4*)&w_sh[col][kq*4] = *(const float4*)&fc1_w[col*64 + kq*4];
    }
    if (tid < 144) b_sh[tid] = fc1_b[tid];
    const int tok0 = blk * 32;
    for (int idx = tid; idx < 32*16; idx += 256) {
        int t = idx >> 4, kq = idx & 15;
        *(float4*)&fe_sh[t][kq*4] = *(const float4*)&g_fe[(size_t)(tok0+t)*64 + kq*4];
    }
    __syncthreads();

    const int cg = tid & 15;
    const int tg = tid >> 4;
    const int c0 = cg * 9;
    const int t0 = tg * 2;

    ull acc[18];
#pragma unroll
    for (int j = 0; j < 18; ++j) acc[j] = 0ull;

#pragma unroll
    for (int kk = 0; kk < 16; ++kk) {
        ulonglong2 f0 = *(const ulonglong2*)&fe_sh[t0][kk*4];
        ulonglong2 f1 = *(const ulonglong2*)&fe_sh[t0+1][kk*4];
#pragma unroll
        for (int j = 0; j < 9; ++j) {
            ulonglong2 w4 = *(const ulonglong2*)&w_sh[c0+j][kk*4];
            acc[j]   = fma2(f0.x, w4.x, acc[j]);
            acc[j]   = fma2(f0.y, w4.y, acc[j]);
            acc[9+j] = fma2(f1.x, w4.x, acc[9+j]);
            acc[9+j] = fma2(f1.y, w4.y, acc[9+j]);
        }
    }
#pragma unroll
    for (int t = 0; t < 2; ++t)
#pragma unroll
        for (int j = 0; j < 9; ++j) {
            float lo, hi; upk2(acc[t*9+j], lo, hi);
            float s = lo + hi + b_sh[c0+j];
            g_H[(size_t)(tok0 + t0 + t)*144 + c0 + j] = fmaxf(s, 0.f);
        }
}

// =======================================================================
// K3: F[tok][i] = LOG2E*(fc2_b[i] + sum_e fc2_w[i][e]*H[tok][e])
// =======================================================================
#define FB_HS 148
#define FB_WS 150
__global__ __launch_bounds__(512, 1) void fbig_kernel(
    const float* __restrict__ fc2_w, const float* __restrict__ fc2_b)
{
    extern __shared__ float fsm[];
    float* Hs = fsm;                    // [128][FB_HS]
    float* Ws = Hs + 128*FB_HS;         // [144][FB_WS]
    float* bs = Ws + 144*FB_WS;         // [144]

    const int tid  = threadIdx.x;
    const int tok0 = blockIdx.x * 128;

    for (int idx = tid; idx < 128*36; idx += 512) {
        int t = idx / 36, kq = idx % 36;
        *(float4*)&Hs[t*FB_HS + kq*4] =
            *(const float4*)&g_H[(size_t)(tok0+t)*144 + kq*4];
    }
    for (int idx = tid; idx < 144*72; idx += 512) {
        int c = idx / 72, kp = idx % 72;
        *(float2*)&Ws[c*FB_WS + kp*2] = *(const float2*)&fc2_w[c*144 + kp*2];
    }
    if (tid < 144) bs[tid] = fc2_b[tid];
    __syncthreads();

    const int tg = tid >> 4;
    const int cg = tid & 15;
    const int t0 = tg * 4;
    const int c0 = cg * 9;

    ull acc[36];
#pragma unroll
    for (int a = 0; a < 36; ++a) acc[a] = 0ull;

#pragma unroll 4
    for (int kp = 0; kp < 72; ++kp) {
        const int kk = kp*2;
        ull hv[4];
#pragma unroll
        for (int j = 0; j < 4; ++j) hv[j] = *(const ull*)&Hs[(t0+j)*FB_HS + kk];
#pragma unroll
        for (int c = 0; c < 9; ++c) {
            ull wv = *(const ull*)&Ws[(c0+c)*FB_WS + kk];
#pragma unroll
            for (int j = 0; j < 4; ++j)
                acc[j*9+c] = fma2(hv[j], wv, acc[j*9+c]);
        }
    }

#pragma unroll
    for (int j = 0; j < 4; ++j)
#pragma unroll
        for (int c = 0; c < 9; ++c) {
            float lo, hi; upk2(acc[j*9+c], lo, hi);
            g_F[(size_t)(tok0 + t0 + j)*144 + c0 + c] =
                LOG2E*(lo + hi + bs[c0+c]);
        }
}

// =======================================================================
// K4: attention v6 — like v5 but P stored as PLAIN floats (no (p,p) dup):
// B2 loads float4 covering 4 queries (16B vs 32B), re-packs in registers.
// =======================================================================
#define S_STR  148
#define KX_STR 18

__global__ __launch_bounds__(576, 2) void attn_kernel()
{
    extern __shared__ __align__(16) char smraw[];
    float* Pf    = (float*)smraw;                  // [48][144] plain
    float* S     = Pf + 48*144;                    // [48][S_STR]
    float* Yt    = S  + 48*S_STR;                  // [48][64]
    float* Kxm   = Yt + 48*64;                     // [48][KX_STR]
    float* xe_sh = Kxm + 48*KX_STR;                // [144][16]
    float* Mt    = xe_sh + 144*16;                 // [4][144]
    float* alS   = Mt + 4*144;                     // [144]
    int*   pm_sh = (int*)(alS + 144);              // [3][144]

    const int cblk = blockIdx.x;
    const int h    = blockIdx.y;
    const int n    = blockIdx.z;
    const int seg  = n*4 + h;
    const int tid  = threadIdx.x;
    const int nbase = n*LL;

    if (tid < 432) {
        int dci = tid / 144, jr = tid % 144;
        int cc = (cblk + (dci == 1 ? 63 : (dci == 2 ? 1 : 0))) & 63;
        pm_sh[tid] = g_perm[seg*LL + cc*CHK + jr];
    }
    __syncthreads();
    for (int idx = tid; idx < 144*4; idx += 576) {
        int i = idx >> 2, c4 = idx & 3;
        int tokg = nbase + pm_sh[i];
        float4 v = *(const float4*)&g_xe[tokg*16 + c4*4];
        v.x *= LOG2E; v.y *= LOG2E; v.z *= LOG2E; v.w *= LOG2E;
        *(float4*)&xe_sh[i*16 + c4*4] = v;
    }

    const int kg = tid % 12;
    const int qg = tid / 12;
    const int q1 = tid % 144;
    const int kg1 = tid / 144;
    const int qg2 = tid >> 4;
    const int eg2 = tid & 15;
    const int q0B = qg2 * 4;

    float m = -1e30f, l = 0.f;
    ull racc[8];
#pragma unroll
    for (int r = 0; r < 8; ++r) racc[r] = 0ull;

    for (int t = 0; t < 9; ++t) {
        const int dc = t / 3;
        const int jr0 = (t % 3) * 48;
        const int pmb = dc*144 + jr0;

        __syncthreads();
        for (int idx = tid; idx < 48*56; idx += 576) {
            int r = idx / 56, c = idx % 56;
            int tokg = nbase + pm_sh[pmb + r];
            if (c < 4) {
                float4 v = *(const float4*)&g_xm[tokg*16 + c*4];
                float* d = &Kxm[r*KX_STR + c*4];
                *(float2*)d     = make_float2(v.x, v.y);
                *(float2*)(d+2) = make_float2(v.z, v.w);
            } else if (c < 40) {
                *(float4*)&S[r*S_STR + (c-4)*4] =
                    *(const float4*)&g_F[(size_t)tokg*144 + (c-4)*4];
            } else {
                *(float4*)&Yt[r*64 + (c-40)*4] =
                    *(const float4*)&g_ye[(size_t)tokg*64 + (c-40)*4];
            }
        }
        __syncthreads();

        // ---- phase A ----
        {
            ull acc[12];
#pragma unroll
            for (int a = 0; a < 12; ++a) acc[a] = 0ull;
#pragma unroll
            for (int dd = 0; dd < 16; dd += 2) {
                ull qa = *(const ull*)&xe_sh[(3*qg+0)*16 + dd];
                ull qb = *(const ull*)&xe_sh[(3*qg+1)*16 + dd];
                ull qc = *(const ull*)&xe_sh[(3*qg+2)*16 + dd];
#pragma unroll
                for (int i = 0; i < 4; ++i) {
                    ull kv = *(const ull*)&Kxm[(kg + 12*i)*KX_STR + dd];
                    acc[0*4+i] = fma2(qa, kv, acc[0*4+i]);
                    acc[1*4+i] = fma2(qb, kv, acc[1*4+i]);
                    acc[2*4+i] = fma2(qc, kv, acc[2*4+i]);
                }
            }
#pragma unroll
            for (int j = 0; j < 3; ++j)
#pragma unroll
                for (int i = 0; i < 4; ++i) {
                    float lo, hi; upk2(acc[j*4+i], lo, hi);
                    S[(kg + 12*i)*S_STR + 3*qg + j] += lo + hi;
                }
        }
        __syncthreads();

        // ---- phase B1: tile max + plain-float P + l quarters ----
        {
            float tm = -1e30f;
#pragma unroll
            for (int j = 0; j < 12; ++j)
                tm = fmaxf(tm, S[(kg1*12 + j)*S_STR + q1]);
            Mt[kg1*144 + q1] = tm;
        }
        __syncthreads();
        {
            float tmax = fmaxf(fmaxf(Mt[q1], Mt[144+q1]),
                               fmaxf(Mt[288+q1], Mt[432+q1]));
            float mn = fmaxf(m, tmax);
            float al = ex2f(m - mn);
            m = mn;
            l *= al;
            if (kg1 == 0) alS[q1] = al;
#pragma unroll
            for (int j = 0; j < 12; ++j) {
                int k = kg1*12 + j;
                float p = ex2f(S[k*S_STR + q1] - mn);
                l += p;
                Pf[k*144 + q1] = p;
            }
        }
        __syncthreads();

        // ---- phase B2: register-tiled P.Y GEMM, float4 P loads ----
        {
            float a0 = alS[q0B], a1 = alS[q0B+1], a2 = alS[q0B+2], a3 = alS[q0B+3];
            racc[0] = mul2_(racc[0], pk2(a0,a0)); racc[1] = mul2_(racc[1], pk2(a0,a0));
            racc[2] = mul2_(racc[2], pk2(a1,a1)); racc[3] = mul2_(racc[3], pk2(a1,a1));
            racc[4] = mul2_(racc[4], pk2(a2,a2)); racc[5] = mul2_(racc[5], pk2(a2,a2));
            racc[6] = mul2_(racc[6], pk2(a3,a3)); racc[7] = mul2_(racc[7], pk2(a3,a3));
#pragma unroll 4
            for (int k = 0; k < 48; ++k) {
                float4 pv = *(const float4*)&Pf[k*144 + q0B];
                ull p0 = pk2(pv.x, pv.x);
                ull p1 = pk2(pv.y, pv.y);
                ull pq2 = pk2(pv.z, pv.z);
                ull p3 = pk2(pv.w, pv.w);
                ulonglong2 yv = *(const ulonglong2*)&Yt[k*64 + eg2*4];
                racc[0] = fma2(p0,  yv.x, racc[0]); racc[1] = fma2(p0,  yv.y, racc[1]);
                racc[2] = fma2(p1,  yv.x, racc[2]); racc[3] = fma2(p1,  yv.y, racc[3]);
                racc[4] = fma2(pq2, yv.x, racc[4]); racc[5] = fma2(pq2, yv.y, racc[5]);
                racc[6] = fma2(p3,  yv.x, racc[6]); racc[7] = fma2(p3,  yv.y, racc[7]);
            }
        }
    }

    // ---- epilogue ----
    __syncthreads();
    Mt[kg1*144 + q1] = l;
    __syncthreads();
    if (tid < 144) {
        float lt = Mt[tid] + Mt[144+tid] + Mt[288+tid] + Mt[432+tid];
        alS[tid] = 1.f / lt;
        g_bsc[seg*LL + pm_sh[tid]] = (m + lg2f(lt)) * LN2;
    }
    __syncthreads();
    {
        float i0 = alS[q0B], i1 = alS[q0B+1], i2 = alS[q0B+2], i3 = alS[q0B+3];
        ull iv0 = pk2(i0,i0), iv1 = pk2(i1,i1), iv2 = pk2(i2,i2), iv3 = pk2(i3,i3);
        const int ebase = eg2*4;
#pragma unroll
        for (int j = 0; j < 4; ++j) {
            ull ivj = (j==0) ? iv0 : (j==1) ? iv1 : (j==2) ? iv2 : iv3;
            int tq = pm_sh[q0B + j];
            ulonglong2 o;
            o.x = mul2_(racc[2*j],   ivj);
            o.y = mul2_(racc[2*j+1], ivj);
            *(ulonglong2*)&g_ret[((size_t)seg*LL + tq)*64 + ebase] = o;
        }
    }
}

// =======================================================================
// K5: per-token softmax over heads + residual, NCHW output
// =======================================================================
__global__ __launch_bounds__(256) void final_kernel(
    const float* __restrict__ x, float* __restrict__ out)
{
    const int tg = blockIdx.x*256 + threadIdx.x;
    const int n = tg / LL, tt = tg % LL;
    float b[4];
    float mx = -1e30f;
#pragma unroll
    for (int h = 0; h < 4; ++h) {
        b[h] = g_bsc[(n*4+h)*LL + tt];
        mx = fmaxf(mx, b[h]);
    }
    float wsum = 0.f;
#pragma unroll
    for (int h = 0; h < 4; ++h) { b[h] = __expf(b[h] - mx); wsum += b[h]; }
    const float inv = 1.f / wsum;
#pragma unroll
    for (int c4 = 0; c4 < 16; ++c4) {
        float4 acc = {0.f, 0.f, 0.f, 0.f};
#pragma unroll
        for (int h = 0; h < 4; ++h) {
            float4 r = *(const float4*)&g_ret[((size_t)(n*4+h)*LL + tt)*64 + c4*4];
            float wv = b[h]*inv;
            acc.x += wv*r.x; acc.y += wv*r.y; acc.z += wv*r.z; acc.w += wv*r.w;
        }
        int c = c4*4;
        out[(n*64+c  )*LL + tt] = acc.x + x[(n*64+c  )*LL + tt];
        out[(n*64+c+1)*LL + tt] = acc.y + x[(n*64+c+1)*LL + tt];
        out[(n*64+c+2)*LL + tt] = acc.z + x[(n*64+c+2)*LL + tt];
        out[(n*64+c+3)*LL + tt] = acc.w + x[(n*64+c+3)*LL + tt];
    }
}

// =======================================================================
extern "C" void kernel_launch(void* const* d_in, const int* in_sizes, int n_in,
                              void* d_out, int out_size)
{
    const float* x     = (const float*)d_in[0];
    const float* rot   = (const float*)d_in[1];
    const float* wm    = (const float*)d_in[2];
    const float* bm    = (const float*)d_in[3];
    const float* wa    = (const float*)d_in[4];
    const float* ba    = (const float*)d_in[5];
    const float* wf    = (const float*)d_in[6];
    const float* bf    = (const float*)d_in[7];
    const float* fc1_w = (const float*)d_in[8];
    const float* fc1_b = (const float*)d_in[9];
    const float* fc2_w = (const float*)d_in[10];
    const float* fc2_b = (const float*)d_in[11];
    float* out = (float*)d_out;

    const int attn_smem = (48*144 + 48*S_STR + 48*64 + 48*KX_STR
                           + 144*16 + 4*144 + 144) * 4 + 432*4;
    const int fbig_smem = (128*FB_HS + 144*FB_WS + 144) * 4;
    cudaFuncSetAttribute(attn_kernel,
                         cudaFuncAttributeMaxDynamicSharedMemorySize, attn_smem);
    cudaFuncSetAttribute(fbig_kernel,
                         cudaFuncAttributeMaxDynamicSharedMemorySize, fbig_smem);

    conv_kernel    <<<dim3(96, 2, 2), dim3(96, 3)>>>(x, rot, wm, bm, wa, ba, wf, bf);
    sorthid_kernel <<<584, 256>>>(fc1_w, fc1_b);
    fbig_kernel    <<<144, 512, fbig_smem>>>(fc2_w, fc2_b);
    attn_kernel    <<<dim3(64, 4, 2), 576, attn_smem>>>();
    final_kernel   <<<72, 256>>>(x, out);
}